// round 10
// baseline (speedup 1.0000x reference)
#include <cuda_runtime.h>
#include <cuda_fp16.h>
#include <math.h>
#include <stdint.h>

#define BATCH 8
#define CH    512
#define NN    1024
#define NH    8
#define HD    64
#define CPG   64
#define GN_EPS 1e-5f

// fp16 scratch
__device__ __half g_w16[(size_t)3 * CH * CH];
__device__ __half g_wp16[(size_t)CH * CH];
__device__ __half g_x16[(size_t)BATCH * CH * NN];
__device__ __half g_qkvh[(size_t)BATCH * 3 * CH * NN];
__device__ __half g_atth[(size_t)BATCH * CH * NN];
__device__ __half g_projh[(size_t)BATCH * CH * NN];
__device__ float  g_part[64 * 8 * 2];

// ---------------------------------------------------------------------------
// helpers
// ---------------------------------------------------------------------------
__device__ __forceinline__ uint32_t smem_u32(const void* p) {
    uint32_t a;
    asm("{ .reg .u64 t; cvta.to.shared.u64 t, %1; cvt.u32.u64 %0, t; }" : "=r"(a) : "l"(p));
    return a;
}
__device__ __forceinline__ uint32_t pk(float x, float y) {
    __half2 h = __floats2half2_rn(x, y);
    return *(uint32_t*)&h;
}
__device__ __forceinline__ uint32_t h2exp2(uint32_t x) {
    uint32_t r;
    asm("ex2.approx.f16x2 %0, %1;" : "=r"(r) : "r"(x));
    return r;
}
__device__ __forceinline__ void mma16816(float* c, const uint32_t* a,
                                         uint32_t b0, uint32_t b1) {
    asm volatile(
        "mma.sync.aligned.m16n8k16.row.col.f32.f16.f16.f32 "
        "{%0,%1,%2,%3},{%4,%5,%6,%7},{%8,%9},{%0,%1,%2,%3};"
        : "+f"(c[0]), "+f"(c[1]), "+f"(c[2]), "+f"(c[3])
        : "r"(a[0]), "r"(a[1]), "r"(a[2]), "r"(a[3]), "r"(b0), "r"(b1));
}
__device__ __forceinline__ void ldsm4(uint32_t* r, uint32_t addr) {
    asm volatile("ldmatrix.sync.aligned.m8n8.x4.shared.b16 {%0,%1,%2,%3}, [%4];"
        : "=r"(r[0]), "=r"(r[1]), "=r"(r[2]), "=r"(r[3]) : "r"(addr));
}
__device__ __forceinline__ void ldsm4t(uint32_t* r, uint32_t addr) {
    asm volatile("ldmatrix.sync.aligned.m8n8.x4.trans.shared.b16 {%0,%1,%2,%3}, [%4];"
        : "=r"(r[0]), "=r"(r[1]), "=r"(r[2]), "=r"(r[3]) : "r"(addr));
}
__device__ __forceinline__ void cp_async16(uint32_t dst, const void* src) {
    asm volatile("cp.async.ca.shared.global [%0], [%1], 16;" :: "r"(dst), "l"(src));
}
#define CP_COMMIT() asm volatile("cp.async.commit_group;" ::: "memory")
#define CP_WAIT(n)  asm volatile("cp.async.wait_group %0;" :: "n"(n) : "memory")

// ---------------------------------------------------------------------------
// single-launch fp32 -> fp16 conversion
// ---------------------------------------------------------------------------
#define CVT_N1 ((3 * CH * CH) / 4)
#define CVT_N2 ((CH * CH) / 4)
#define CVT_N3 ((BATCH * CH * NN) / 4)
__global__ __launch_bounds__(256) void cvt_all(
    const float* __restrict__ w, __half* __restrict__ w16,
    const float* __restrict__ wp, __half* __restrict__ wp16,
    const float* __restrict__ x, __half* __restrict__ x16)
{
    const int total = CVT_N1 + CVT_N2 + CVT_N3;
    for (int i = blockIdx.x * 256 + threadIdx.x; i < total; i += gridDim.x * 256) {
        const float* s; __half* d; int j;
        if (i < CVT_N1)                { s = w;  d = w16;  j = i; }
        else if (i < CVT_N1 + CVT_N2)  { s = wp; d = wp16; j = i - CVT_N1; }
        else                           { s = x;  d = x16;  j = i - CVT_N1 - CVT_N2; }
        float4 v = *(const float4*)&s[(size_t)j * 4];
        *(uint2*)&d[(size_t)j * 4] = make_uint2(pk(v.x, v.y), pk(v.z, v.w));
    }
}

// ---------------------------------------------------------------------------
// all-fp16 cp.async 3-stage GEMM. CTA 256x128, warp tile 64x64. (unchanged)
// ---------------------------------------------------------------------------
#define LDA 40
#define LDB 136
#define STG_A (256 * LDA)
#define STG_B (32 * LDB)
#define STG_H (STG_A + STG_B)
#define GSMEM (3 * STG_H * 2)

template<typename TC, bool SCALEQ>
__global__ __launch_bounds__(256) void gemm_a(
    const __half* __restrict__ A, const __half* __restrict__ Bg,
    TC* __restrict__ Cg, int M, int N, int K)
{
    extern __shared__ __half sh[];

    const int bz = blockIdx.z;
    const __half* Bp = Bg + (size_t)bz * K * N;
    TC*           Cp = Cg + (size_t)bz * M * N;

    const int tid = threadIdx.x;
    const int warp = tid >> 5, lane = tid & 31;
    const int wm = warp >> 1, wn = warp & 1;
    const int g = lane >> 2, t = lane & 3;
    const int row0 = blockIdx.y * 256;
    const int col0 = blockIdx.x * 128;
    const uint32_t sb = smem_u32(sh);
    const int nk = K / 32;

    auto issue = [&](int kt, int st) {
        const uint32_t sau = sb + st * STG_H * 2;
        const uint32_t sbu = sau + STG_A * 2;
        #pragma unroll
        for (int i = 0; i < 4; i++) {
            int idx = tid + i * 256;
            int r = idx >> 2, ch = idx & 3;
            cp_async16(sau + (r * LDA + ch * 8) * 2,
                       A + (size_t)(row0 + r) * K + kt * 32 + ch * 8);
        }
        #pragma unroll
        for (int i = 0; i < 2; i++) {
            int idx = tid + i * 256;
            int r = idx >> 4, ch = idx & 15;
            cp_async16(sbu + (r * LDB + ch * 8) * 2,
                       Bp + (size_t)(kt * 32 + r) * N + col0 + ch * 8);
        }
        CP_COMMIT();
    };

    float acc[4][8][4];
    #pragma unroll
    for (int i = 0; i < 4; i++)
        #pragma unroll
        for (int j = 0; j < 8; j++)
            #pragma unroll
            for (int e = 0; e < 4; e++) acc[i][j][e] = 0.f;

    issue(0, 0);
    issue(1, 1);

    const uint32_t aLane = (((wm * 64 + (lane & 15)) * LDA) + 8 * (lane >> 4)) * 2;
    const uint32_t bLane = ((((lane & 7) + 8 * ((lane >> 3) & 1)) * LDB)
                            + wn * 64 + 8 * (lane >> 4)) * 2;

    for (int kt = 0; kt < nk; kt++) {
        const int st = kt % 3;
        if (kt + 1 < nk) { CP_WAIT(1); } else { CP_WAIT(0); }
        __syncthreads();
        if (kt + 2 < nk) issue(kt + 2, (kt + 2) % 3);

        const uint32_t aAddr = sb + st * STG_H * 2 + aLane;
        const uint32_t bAddr = sb + st * STG_H * 2 + STG_A * 2 + bLane;
        #pragma unroll
        for (int ks = 0; ks < 2; ks++) {
            uint32_t a[4][4];
            #pragma unroll
            for (int mi = 0; mi < 4; mi++)
                ldsm4(a[mi], aAddr + ks * 32 + mi * 16 * LDA * 2);
            #pragma unroll
            for (int jj = 0; jj < 4; jj++) {
                uint32_t b[4];
                ldsm4t(b, bAddr + ks * 16 * LDB * 2 + jj * 32);
                #pragma unroll
                for (int mi = 0; mi < 4; mi++) {
                    mma16816(acc[mi][2 * jj],     a[mi], b[0], b[1]);
                    mma16816(acc[mi][2 * jj + 1], a[mi], b[2], b[3]);
                }
            }
        }
    }

    const float cs = (SCALEQ && row0 < 512) ? 0.125f * 1.44269504f : 1.f;
    #pragma unroll
    for (int mi = 0; mi < 4; mi++) {
        int r = row0 + wm * 64 + mi * 16 + g;
        #pragma unroll
        for (int j = 0; j < 8; j++) {
            int c = col0 + wn * 64 + 8 * j + 2 * t;
            if constexpr (sizeof(TC) == 2) {
                *(uint32_t*)&Cp[(size_t)r * N + c] =
                    pk(acc[mi][j][0] * cs, acc[mi][j][1] * cs);
                *(uint32_t*)&Cp[(size_t)(r + 8) * N + c] =
                    pk(acc[mi][j][2] * cs, acc[mi][j][3] * cs);
            } else {
                *(float2*)&Cp[(size_t)r * N + c] =
                    make_float2(acc[mi][j][0] * cs, acc[mi][j][1] * cs);
                *(float2*)&Cp[(size_t)(r + 8) * N + c] =
                    make_float2(acc[mi][j][2] * cs, acc[mi][j][3] * cs);
            }
        }
    }
}

// ---------------------------------------------------------------------------
// Fused flash attention: 256 query rows/CTA (8 warps), f16x2 exp softmax.
// qs: [64 d][264 n]; ks/vs: 2 stages x [64 d][72 m].
// ---------------------------------------------------------------------------
#define LDQ 264
#define LDK 72
#define LDO 72
#define ATT_SMEM ((64 * LDQ + 4 * 64 * LDK) * 2)

__global__ __launch_bounds__(256) void attn_h(
    const __half* __restrict__ qkv, __half* __restrict__ outh)
{
    extern __shared__ __half smh[];
    __half* qs = smh;
    __half* kv = smh + 64 * LDQ;

    const int b = blockIdx.z, h = blockIdx.y;
    const int n0 = blockIdx.x * 256;
    const int tid = threadIdx.x, warp = tid >> 5, lane = tid & 31;
    const int g = lane >> 2, t = lane & 3;
    const int rowbase = warp * 32;

    const __half* q = qkv + (((size_t)b * 3 + 0) * NH + h) * HD * NN;
    const __half* k = qkv + (((size_t)b * 3 + 1) * NH + h) * HD * NN;
    const __half* v = qkv + (((size_t)b * 3 + 2) * NH + h) * HD * NN;

    const uint32_t qb  = smem_u32(qs);
    const uint32_t kvb = smem_u32(kv);
    const uint32_t qLane = ((((lane & 7) + 8 * (lane >> 4)) * LDQ)
                            + rowbase + 8 * ((lane >> 3) & 1)) * 2;
    const uint32_t kLane = ((((lane & 7) + 8 * ((lane >> 3) & 1)) * LDK)
                            + 8 * (lane >> 4)) * 2;
    const uint32_t vLane = ((((lane & 7) + 8 * (lane >> 4)) * LDK)
                            + 8 * ((lane >> 3) & 1)) * 2;

    auto issueKV = [&](int mt, int st) {
        const int m0 = mt * 64;
        const uint32_t kd = kvb + st * (2 * 64 * LDK) * 2;
        const uint32_t vd = kd + (64 * LDK) * 2;
        #pragma unroll
        for (int i = 0; i < 2; i++) {
            int idx = tid + i * 256;
            int d = idx >> 3, ch = idx & 7;
            cp_async16(kd + (d * LDK + ch * 8) * 2, k + (size_t)d * NN + m0 + ch * 8);
            cp_async16(vd + (d * LDK + ch * 8) * 2, v + (size_t)d * NN + m0 + ch * 8);
        }
    };

    // Q: 64 d-rows x 256 n = 64x32 chunks, 8/thread
    #pragma unroll
    for (int i = 0; i < 8; i++) {
        int idx = tid + i * 256;
        int d = idx >> 5, ch = idx & 31;
        cp_async16(qb + (d * LDQ + ch * 8) * 2, q + (size_t)d * NN + n0 + ch * 8);
    }
    issueKV(0, 0);
    CP_COMMIT();

    float o[2][8][4];
    float Mx[2][2], L[2][2];
    #pragma unroll
    for (int i = 0; i < 2; i++) {
        #pragma unroll
        for (int j = 0; j < 8; j++)
            #pragma unroll
            for (int e = 0; e < 4; e++) o[i][j][e] = 0.f;
        Mx[i][0] = Mx[i][1] = -1e30f;
        L[i][0] = L[i][1] = 0.f;
    }

    for (int mt = 0; mt < NN / 64; mt++) {
        const int st = mt & 1;
        if (mt + 1 < NN / 64) {
            issueKV(mt + 1, st ^ 1);
            CP_COMMIT();
            CP_WAIT(1);
        } else {
            CP_WAIT(0);
        }
        __syncthreads();

        const uint32_t kAddr = kvb + st * (2 * 64 * LDK) * 2 + kLane;
        const uint32_t vAddr = kvb + st * (2 * 64 * LDK) * 2 + (64 * LDK) * 2 + vLane;

        // ---- S = Q * K^T ----
        float s[2][8][4];
        #pragma unroll
        for (int i = 0; i < 2; i++)
            #pragma unroll
            for (int j = 0; j < 8; j++)
                #pragma unroll
                for (int e = 0; e < 4; e++) s[i][j][e] = 0.f;

        #pragma unroll
        for (int ks16 = 0; ks16 < 4; ks16++) {
            uint32_t a[2][4];
            ldsm4t(a[0], qb + qLane + ks16 * 16 * LDQ * 2);
            ldsm4t(a[1], qb + qLane + ks16 * 16 * LDQ * 2 + 32);
            #pragma unroll
            for (int jj = 0; jj < 4; jj++) {
                uint32_t bf[4];
                ldsm4t(bf, kAddr + ks16 * 16 * LDK * 2 + jj * 32);
                mma16816(s[0][2 * jj],     a[0], bf[0], bf[1]);
                mma16816(s[0][2 * jj + 1], a[0], bf[2], bf[3]);
                mma16816(s[1][2 * jj],     a[1], bf[0], bf[1]);
                mma16816(s[1][2 * jj + 1], a[1], bf[2], bf[3]);
            }
        }

        // ---- online softmax: f16x2 exp producing P fragments directly ----
        uint32_t P[2][2][8];
        #pragma unroll
        for (int i = 0; i < 2; i++) {
            #pragma unroll
            for (int rh = 0; rh < 2; rh++) {
                float tm = -1e30f;
                #pragma unroll
                for (int j = 0; j < 8; j++)
                    tm = fmaxf(tm, fmaxf(s[i][j][2 * rh], s[i][j][2 * rh + 1]));
                tm = fmaxf(tm, __shfl_xor_sync(0xffffffffu, tm, 1));
                tm = fmaxf(tm, __shfl_xor_sync(0xffffffffu, tm, 2));
                float nM = fmaxf(Mx[i][rh], tm);
                float corr = exp2f(Mx[i][rh] - nM);
                Mx[i][rh] = nM;
                float ls = 0.f;
                #pragma unroll
                for (int j = 0; j < 8; j++) {
                    uint32_t pe = h2exp2(pk(s[i][j][2 * rh] - nM,
                                            s[i][j][2 * rh + 1] - nM));
                    P[i][rh][j] = pe;
                    float2 f = __half22float2(*(__half2*)&pe);
                    ls += f.x + f.y;
                }
                ls += __shfl_xor_sync(0xffffffffu, ls, 1);
                ls += __shfl_xor_sync(0xffffffffu, ls, 2);
                L[i][rh] = L[i][rh] * corr + ls;
                #pragma unroll
                for (int j = 0; j < 8; j++) {
                    o[i][j][2 * rh]     *= corr;
                    o[i][j][2 * rh + 1] *= corr;
                }
            }
        }

        // ---- O += P * V^T ----
        #pragma unroll
        for (int ms2 = 0; ms2 < 4; ms2++) {
            uint32_t aP[2][4];
            #pragma unroll
            for (int i = 0; i < 2; i++) {
                aP[i][0] = P[i][0][2 * ms2];
                aP[i][1] = P[i][1][2 * ms2];
                aP[i][2] = P[i][0][2 * ms2 + 1];
                aP[i][3] = P[i][1][2 * ms2 + 1];
            }
            #pragma unroll
            for (int jj = 0; jj < 4; jj++) {
                uint32_t bf[4];
                ldsm4(bf, vAddr + jj * 16 * LDK * 2 + ms2 * 32);
                mma16816(o[0][2 * jj],     aP[0], bf[0], bf[1]);
                mma16816(o[0][2 * jj + 1], aP[0], bf[2], bf[3]);
                mma16816(o[1][2 * jj],     aP[1], bf[0], bf[1]);
                mma16816(o[1][2 * jj + 1], aP[1], bf[2], bf[3]);
            }
        }
        __syncthreads();
    }

    // ---- epilogue: smem transpose -> coalesced fp16 stores ----
    __half* os = smh;   // reuse: [256 n][LDO d]
    #pragma unroll
    for (int i = 0; i < 2; i++) {
        float inv0 = 1.f / L[i][0];
        float inv1 = 1.f / L[i][1];
        int rl = rowbase + 16 * i + g;
        #pragma unroll
        for (int j = 0; j < 8; j++) {
            int d = 8 * j + 2 * t;
            *(uint32_t*)&os[rl * LDO + d]       = pk(o[i][j][0] * inv0, o[i][j][1] * inv0);
            *(uint32_t*)&os[(rl + 8) * LDO + d] = pk(o[i][j][2] * inv1, o[i][j][3] * inv1);
        }
    }
    __syncthreads();
    {
        const int d = tid >> 2, seg = (tid & 3) * 64;
        __half* dst = outh + ((size_t)b * CH + h * HD + d) * NN + n0 + seg;
        #pragma unroll
        for (int c8 = 0; c8 < 8; c8++) {
            __half tmp[8];
            #pragma unroll
            for (int r = 0; r < 8; r++)
                tmp[r] = os[(seg + c8 * 8 + r) * LDO + d];
            *(uint4*)&dst[c8 * 8] = *(uint4*)tmp;
        }
    }
}

// ---------------------------------------------------------------------------
// GroupNorm two-pass over fp16 proj (unchanged)
// ---------------------------------------------------------------------------
__global__ __launch_bounds__(256) void gn_stat(const __half* __restrict__ p)
{
    const int bg = blockIdx.x >> 3, sp = blockIdx.x & 7;
    const uint4* p8 = (const uint4*)(p + (size_t)bg * CPG * NN) + sp * 1024;
    float sum = 0.f, ss = 0.f;
    #pragma unroll
    for (int it = 0; it < 4; it++) {
        uint4 u = p8[threadIdx.x + it * 256];
        const __half2* hp = (const __half2*)&u;
        #pragma unroll
        for (int j = 0; j < 4; j++) {
            float2 f = __half22float2(hp[j]);
            sum += f.x + f.y;
            ss  += f.x * f.x + f.y * f.y;
        }
    }
    #pragma unroll
    for (int off = 16; off; off >>= 1) {
        sum += __shfl_xor_sync(0xffffffffu, sum, off);
        ss  += __shfl_xor_sync(0xffffffffu, ss, off);
    }
    __shared__ float rs[8], rq[8];
    const int warp = threadIdx.x >> 5;
    if ((threadIdx.x & 31) == 0) { rs[warp] = sum; rq[warp] = ss; }
    __syncthreads();
    if (threadIdx.x == 0) {
        float s = 0.f, q = 0.f;
        #pragma unroll
        for (int w = 0; w < 8; w++) { s += rs[w]; q += rq[w]; }
        g_part[blockIdx.x * 2]     = s;
        g_part[blockIdx.x * 2 + 1] = q;
    }
}

__global__ __launch_bounds__(256) void gn_apply(
    const __half* __restrict__ p, const float* __restrict__ x,
    const float* __restrict__ gamma, const float* __restrict__ beta,
    float* __restrict__ out)
{
    const int bg = blockIdx.x >> 3, sp = blockIdx.x & 7;
    float sum = 0.f, ss = 0.f;
    #pragma unroll
    for (int i = 0; i < 8; i++) {
        sum += g_part[(bg * 8 + i) * 2];
        ss  += g_part[(bg * 8 + i) * 2 + 1];
    }
    const float invn = 1.f / 65536.f;
    const float mean = sum * invn;
    const float inv  = rsqrtf(ss * invn - mean * mean + GN_EPS);
    const int grp = bg & 7;

    const size_t base = (size_t)bg * CPG * NN;
    const uint4*  p8 = (const uint4*)(p + base) + sp * 1024;
    const float4* x4 = (const float4*)(x + base) + sp * 2048;
    float4*       o4 = (float4*)(out + base) + sp * 2048;

    #pragma unroll
    for (int it = 0; it < 4; it++) {
        int idx = threadIdx.x + it * 256;
        int c = grp * CPG + sp * 8 + (idx >> 7);
        float ga = gamma[c] * inv, be = beta[c];
        uint4 u = p8[idx];
        const __half2* hp = (const __half2*)&u;
        float4 xa = x4[2 * idx], xb = x4[2 * idx + 1];
        float2 f0 = __half22float2(hp[0]), f1 = __half22float2(hp[1]);
        float2 f2 = __half22float2(hp[2]), f3 = __half22float2(hp[3]);
        float4 ra, rb;
        ra.x = (f0.x - mean) * ga + be + xa.x;
        ra.y = (f0.y - mean) * ga + be + xa.y;
        ra.z = (f1.x - mean) * ga + be + xa.z;
        ra.w = (f1.y - mean) * ga + be + xa.w;
        rb.x = (f2.x - mean) * ga + be + xb.x;
        rb.y = (f2.y - mean) * ga + be + xb.y;
        rb.z = (f3.x - mean) * ga + be + xb.z;
        rb.w = (f3.y - mean) * ga + be + xb.w;
        o4[2 * idx]     = ra;
        o4[2 * idx + 1] = rb;
    }
}

// ---------------------------------------------------------------------------
extern "C" void kernel_launch(void* const* d_in, const int* in_sizes, int n_in,
                              void* d_out, int out_size)
{
    const float* x      = (const float*)d_in[0];
    const float* w_qkv  = (const float*)d_in[1];
    const float* w_proj = (const float*)d_in[2];
    const float* gamma  = (const float*)d_in[3];
    const float* beta   = (const float*)d_in[4];
    float* out = (float*)d_out;

    __half *w16, *wp16, *x16, *qkvh, *atth, *projh;
    cudaGetSymbolAddress((void**)&w16,   g_w16);
    cudaGetSymbolAddress((void**)&wp16,  g_wp16);
    cudaGetSymbolAddress((void**)&x16,   g_x16);
    cudaGetSymbolAddress((void**)&qkvh,  g_qkvh);
    cudaGetSymbolAddress((void**)&atth,  g_atth);
    cudaGetSymbolAddress((void**)&projh, g_projh);

    static bool attr_set = false;
    if (!attr_set) {
        cudaFuncSetAttribute(attn_h,
            cudaFuncAttributeMaxDynamicSharedMemorySize, ATT_SMEM);
        cudaFuncSetAttribute((const void*)gemm_a<__half, true>,
            cudaFuncAttributeMaxDynamicSharedMemorySize, GSMEM);
        cudaFuncSetAttribute((const void*)gemm_a<__half, false>,
            cudaFuncAttributeMaxDynamicSharedMemorySize, GSMEM);
        attr_set = true;
    }

    // 0) single-launch fp32 -> fp16 conversion
    cvt_all<<<1280, 256>>>(w_qkv, w16, w_proj, wp16, x, x16);

    // 1) QKV projection (Q rows scaled by 0.125*log2e)
    gemm_a<__half, true><<<dim3(NN / 128, (3 * CH) / 256, BATCH), 256, GSMEM>>>(
        w16, x16, qkvh, 3 * CH, NN, CH);

    // 2) Fused flash attention (256-row query tiles)
    attn_h<<<dim3(NN / 256, NH, BATCH), 256, ATT_SMEM>>>(qkvh, atth);

    // 3) Output projection -> fp16
    gemm_a<__half, false><<<dim3(NN / 128, CH / 256, BATCH), 256, GSMEM>>>(
        wp16, atth, projh, CH, NN, CH);

    // 4) GroupNorm + affine + residual
    gn_stat<<<512, 256>>>(projh);
    gn_apply<<<512, 256>>>(projh, x, gamma, beta, out);
}

// round 11
// speedup vs baseline: 1.0126x; 1.0126x over previous
#include <cuda_runtime.h>
#include <cuda_fp16.h>
#include <math.h>
#include <stdint.h>

#define BATCH 8
#define CH    512
#define NN    1024
#define NH    8
#define HD    64
#define CPG   64
#define GN_EPS 1e-5f

// fp16 scratch
__device__ __half g_w16[(size_t)3 * CH * CH];
__device__ __half g_wp16[(size_t)CH * CH];
__device__ __half g_x16[(size_t)BATCH * CH * NN];
__device__ __half g_qkvh[(size_t)BATCH * 3 * CH * NN];
__device__ __half g_atth[(size_t)BATCH * CH * NN];
__device__ __half g_projh[(size_t)BATCH * CH * NN];
__device__ float  g_part[64 * 8 * 2];

// ---------------------------------------------------------------------------
// helpers
// ---------------------------------------------------------------------------
__device__ __forceinline__ uint32_t smem_u32(const void* p) {
    uint32_t a;
    asm("{ .reg .u64 t; cvta.to.shared.u64 t, %1; cvt.u32.u64 %0, t; }" : "=r"(a) : "l"(p));
    return a;
}
__device__ __forceinline__ uint32_t pk(float x, float y) {
    __half2 h = __floats2half2_rn(x, y);
    return *(uint32_t*)&h;
}
__device__ __forceinline__ uint32_t h2exp2(uint32_t x) {
    uint32_t r;
    asm("ex2.approx.f16x2 %0, %1;" : "=r"(r) : "r"(x));
    return r;
}
__device__ __forceinline__ void mma16816(float* c, const uint32_t* a,
                                         uint32_t b0, uint32_t b1) {
    asm volatile(
        "mma.sync.aligned.m16n8k16.row.col.f32.f16.f16.f32 "
        "{%0,%1,%2,%3},{%4,%5,%6,%7},{%8,%9},{%0,%1,%2,%3};"
        : "+f"(c[0]), "+f"(c[1]), "+f"(c[2]), "+f"(c[3])
        : "r"(a[0]), "r"(a[1]), "r"(a[2]), "r"(a[3]), "r"(b0), "r"(b1));
}
__device__ __forceinline__ void ldsm4(uint32_t* r, uint32_t addr) {
    asm volatile("ldmatrix.sync.aligned.m8n8.x4.shared.b16 {%0,%1,%2,%3}, [%4];"
        : "=r"(r[0]), "=r"(r[1]), "=r"(r[2]), "=r"(r[3]) : "r"(addr));
}
__device__ __forceinline__ void ldsm4t(uint32_t* r, uint32_t addr) {
    asm volatile("ldmatrix.sync.aligned.m8n8.x4.trans.shared.b16 {%0,%1,%2,%3}, [%4];"
        : "=r"(r[0]), "=r"(r[1]), "=r"(r[2]), "=r"(r[3]) : "r"(addr));
}
__device__ __forceinline__ void cp_async16(uint32_t dst, const void* src) {
    asm volatile("cp.async.ca.shared.global [%0], [%1], 16;" :: "r"(dst), "l"(src));
}
#define CP_COMMIT() asm volatile("cp.async.commit_group;" ::: "memory")
#define CP_WAIT(n)  asm volatile("cp.async.wait_group %0;" :: "n"(n) : "memory")

// ---------------------------------------------------------------------------
// single-launch fp32 -> fp16 conversion
// ---------------------------------------------------------------------------
#define CVT_N1 ((3 * CH * CH) / 4)
#define CVT_N2 ((CH * CH) / 4)
#define CVT_N3 ((BATCH * CH * NN) / 4)
__global__ __launch_bounds__(256) void cvt_all(
    const float* __restrict__ w, __half* __restrict__ w16,
    const float* __restrict__ wp, __half* __restrict__ wp16,
    const float* __restrict__ x, __half* __restrict__ x16)
{
    const int total = CVT_N1 + CVT_N2 + CVT_N3;
    for (int i = blockIdx.x * 256 + threadIdx.x; i < total; i += gridDim.x * 256) {
        const float* s; __half* d; int j;
        if (i < CVT_N1)                { s = w;  d = w16;  j = i; }
        else if (i < CVT_N1 + CVT_N2)  { s = wp; d = wp16; j = i - CVT_N1; }
        else                           { s = x;  d = x16;  j = i - CVT_N1 - CVT_N2; }
        float4 v = *(const float4*)&s[(size_t)j * 4];
        *(uint2*)&d[(size_t)j * 4] = make_uint2(pk(v.x, v.y), pk(v.z, v.w));
    }
}

// ---------------------------------------------------------------------------
// all-fp16 cp.async 3-stage GEMM. 8 warps (4x2), warp tile (MI*16)x64,
// CTA tile (MI*64)x128, k-tile 32. MI=4 for QKV, MI=2 for proj.
// ---------------------------------------------------------------------------
#define LDA 40
#define LDB 136
#define STG_B (32 * LDB)
template<int MI> struct GCfg {
    static constexpr int MTILE = MI * 64;
    static constexpr int STG_A = MTILE * LDA;
    static constexpr int STG_H = STG_A + STG_B;
    static constexpr int SMEM  = 3 * STG_H * 2;
};

template<typename TC, bool SCALEQ, int MI>
__global__ __launch_bounds__(256) void gemm_a(
    const __half* __restrict__ A, const __half* __restrict__ Bg,
    TC* __restrict__ Cg, int M, int N, int K)
{
    extern __shared__ __half sh[];
    constexpr int MTILE = GCfg<MI>::MTILE;
    constexpr int STG_A = GCfg<MI>::STG_A;
    constexpr int STG_H = GCfg<MI>::STG_H;

    const int bz = blockIdx.z;
    const __half* Bp = Bg + (size_t)bz * K * N;
    TC*           Cp = Cg + (size_t)bz * M * N;

    const int tid = threadIdx.x;
    const int warp = tid >> 5, lane = tid & 31;
    const int wm = warp >> 1, wn = warp & 1;
    const int g = lane >> 2, t = lane & 3;
    const int row0 = blockIdx.y * MTILE;
    const int col0 = blockIdx.x * 128;
    const uint32_t sb = smem_u32(sh);
    const int nk = K / 32;

    auto issue = [&](int kt, int st) {
        const uint32_t sau = sb + st * STG_H * 2;
        const uint32_t sbu = sau + STG_A * 2;
        #pragma unroll
        for (int i = 0; i < MI; i++) {
            int idx = tid + i * 256;
            int r = idx >> 2, ch = idx & 3;
            cp_async16(sau + (r * LDA + ch * 8) * 2,
                       A + (size_t)(row0 + r) * K + kt * 32 + ch * 8);
        }
        #pragma unroll
        for (int i = 0; i < 2; i++) {
            int idx = tid + i * 256;
            int r = idx >> 4, ch = idx & 15;
            cp_async16(sbu + (r * LDB + ch * 8) * 2,
                       Bp + (size_t)(kt * 32 + r) * N + col0 + ch * 8);
        }
        CP_COMMIT();
    };

    float acc[MI][8][4];
    #pragma unroll
    for (int i = 0; i < MI; i++)
        #pragma unroll
        for (int j = 0; j < 8; j++)
            #pragma unroll
            for (int e = 0; e < 4; e++) acc[i][j][e] = 0.f;

    issue(0, 0);
    issue(1, 1);

    const uint32_t aLane = (((wm * (MI * 16) + (lane & 15)) * LDA) + 8 * (lane >> 4)) * 2;
    const uint32_t bLane = ((((lane & 7) + 8 * ((lane >> 3) & 1)) * LDB)
                            + wn * 64 + 8 * (lane >> 4)) * 2;

    for (int kt = 0; kt < nk; kt++) {
        const int st = kt % 3;
        if (kt + 1 < nk) { CP_WAIT(1); } else { CP_WAIT(0); }
        __syncthreads();
        if (kt + 2 < nk) issue(kt + 2, (kt + 2) % 3);

        const uint32_t aAddr = sb + st * STG_H * 2 + aLane;
        const uint32_t bAddr = sb + st * STG_H * 2 + STG_A * 2 + bLane;
        #pragma unroll
        for (int ks = 0; ks < 2; ks++) {
            uint32_t a[MI][4];
            #pragma unroll
            for (int mi = 0; mi < MI; mi++)
                ldsm4(a[mi], aAddr + ks * 32 + mi * 16 * LDA * 2);
            #pragma unroll
            for (int jj = 0; jj < 4; jj++) {
                uint32_t b[4];
                ldsm4t(b, bAddr + ks * 16 * LDB * 2 + jj * 32);
                #pragma unroll
                for (int mi = 0; mi < MI; mi++) {
                    mma16816(acc[mi][2 * jj],     a[mi], b[0], b[1]);
                    mma16816(acc[mi][2 * jj + 1], a[mi], b[2], b[3]);
                }
            }
        }
    }

    const float cs = (SCALEQ && row0 < 512) ? 0.125f * 1.44269504f : 1.f;
    #pragma unroll
    for (int mi = 0; mi < MI; mi++) {
        int r = row0 + wm * (MI * 16) + mi * 16 + g;
        #pragma unroll
        for (int j = 0; j < 8; j++) {
            int c = col0 + wn * 64 + 8 * j + 2 * t;
            if constexpr (sizeof(TC) == 2) {
                *(uint32_t*)&Cp[(size_t)r * N + c] =
                    pk(acc[mi][j][0] * cs, acc[mi][j][1] * cs);
                *(uint32_t*)&Cp[(size_t)(r + 8) * N + c] =
                    pk(acc[mi][j][2] * cs, acc[mi][j][3] * cs);
            } else {
                *(float2*)&Cp[(size_t)r * N + c] =
                    make_float2(acc[mi][j][0] * cs, acc[mi][j][1] * cs);
                *(float2*)&Cp[(size_t)(r + 8) * N + c] =
                    make_float2(acc[mi][j][2] * cs, acc[mi][j][3] * cs);
            }
        }
    }
}

// ---------------------------------------------------------------------------
// Fused flash attention (R8 shape: 128 rows, 4 warps) + f16x2 exp softmax.
// ---------------------------------------------------------------------------
#define LDQ 136
#define LDK 72
#define LDO 72
#define ATT_SMEM ((64 * LDQ + 4 * 64 * LDK) * 2)

__global__ __launch_bounds__(128) void attn_h(
    const __half* __restrict__ qkv, __half* __restrict__ outh)
{
    extern __shared__ __half smh[];
    __half* qs = smh;
    __half* kv = smh + 64 * LDQ;

    const int b = blockIdx.z, h = blockIdx.y;
    const int n0 = blockIdx.x * 128;
    const int tid = threadIdx.x, warp = tid >> 5, lane = tid & 31;
    const int g = lane >> 2, t = lane & 3;
    const int rowbase = warp * 32;

    const __half* q = qkv + (((size_t)b * 3 + 0) * NH + h) * HD * NN;
    const __half* k = qkv + (((size_t)b * 3 + 1) * NH + h) * HD * NN;
    const __half* v = qkv + (((size_t)b * 3 + 2) * NH + h) * HD * NN;

    const uint32_t qb  = smem_u32(qs);
    const uint32_t kvb = smem_u32(kv);
    const uint32_t qLane = ((((lane & 7) + 8 * (lane >> 4)) * LDQ)
                            + rowbase + 8 * ((lane >> 3) & 1)) * 2;
    const uint32_t kLane = ((((lane & 7) + 8 * ((lane >> 3) & 1)) * LDK)
                            + 8 * (lane >> 4)) * 2;
    const uint32_t vLane = ((((lane & 7) + 8 * (lane >> 4)) * LDK)
                            + 8 * ((lane >> 3) & 1)) * 2;

    auto issueKV = [&](int mt, int st) {
        const int m0 = mt * 64;
        const uint32_t kd = kvb + st * (2 * 64 * LDK) * 2;
        const uint32_t vd = kd + (64 * LDK) * 2;
        #pragma unroll
        for (int i = 0; i < 4; i++) {
            int idx = tid + i * 128;
            int d = idx >> 3, ch = idx & 7;
            cp_async16(kd + (d * LDK + ch * 8) * 2, k + (size_t)d * NN + m0 + ch * 8);
            cp_async16(vd + (d * LDK + ch * 8) * 2, v + (size_t)d * NN + m0 + ch * 8);
        }
    };

    #pragma unroll
    for (int i = 0; i < 8; i++) {
        int idx = tid + i * 128;
        int d = idx >> 4, ch = idx & 15;
        cp_async16(qb + (d * LDQ + ch * 8) * 2, q + (size_t)d * NN + n0 + ch * 8);
    }
    issueKV(0, 0);
    CP_COMMIT();

    float o[2][8][4];
    float Mx[2][2], L[2][2];
    #pragma unroll
    for (int i = 0; i < 2; i++) {
        #pragma unroll
        for (int j = 0; j < 8; j++)
            #pragma unroll
            for (int e = 0; e < 4; e++) o[i][j][e] = 0.f;
        Mx[i][0] = Mx[i][1] = -1e30f;
        L[i][0] = L[i][1] = 0.f;
    }

    for (int mt = 0; mt < NN / 64; mt++) {
        const int st = mt & 1;
        if (mt + 1 < NN / 64) {
            issueKV(mt + 1, st ^ 1);
            CP_COMMIT();
            CP_WAIT(1);
        } else {
            CP_WAIT(0);
        }
        __syncthreads();

        const uint32_t kAddr = kvb + st * (2 * 64 * LDK) * 2 + kLane;
        const uint32_t vAddr = kvb + st * (2 * 64 * LDK) * 2 + (64 * LDK) * 2 + vLane;

        // ---- S = Q * K^T ----
        float s[2][8][4];
        #pragma unroll
        for (int i = 0; i < 2; i++)
            #pragma unroll
            for (int j = 0; j < 8; j++)
                #pragma unroll
                for (int e = 0; e < 4; e++) s[i][j][e] = 0.f;

        #pragma unroll
        for (int ks16 = 0; ks16 < 4; ks16++) {
            uint32_t a[2][4];
            ldsm4t(a[0], qb + qLane + ks16 * 16 * LDQ * 2);
            ldsm4t(a[1], qb + qLane + ks16 * 16 * LDQ * 2 + 32);
            #pragma unroll
            for (int jj = 0; jj < 4; jj++) {
                uint32_t bf[4];
                ldsm4t(bf, kAddr + ks16 * 16 * LDK * 2 + jj * 32);
                mma16816(s[0][2 * jj],     a[0], bf[0], bf[1]);
                mma16816(s[0][2 * jj + 1], a[0], bf[2], bf[3]);
                mma16816(s[1][2 * jj],     a[1], bf[0], bf[1]);
                mma16816(s[1][2 * jj + 1], a[1], bf[2], bf[3]);
            }
        }

        // ---- online softmax: f16x2 exp -> P fragments directly ----
        uint32_t P[2][2][8];
        #pragma unroll
        for (int i = 0; i < 2; i++) {
            #pragma unroll
            for (int rh = 0; rh < 2; rh++) {
                float tm = -1e30f;
                #pragma unroll
                for (int j = 0; j < 8; j++)
                    tm = fmaxf(tm, fmaxf(s[i][j][2 * rh], s[i][j][2 * rh + 1]));
                tm = fmaxf(tm, __shfl_xor_sync(0xffffffffu, tm, 1));
                tm = fmaxf(tm, __shfl_xor_sync(0xffffffffu, tm, 2));
                float nM = fmaxf(Mx[i][rh], tm);
                float corr = exp2f(Mx[i][rh] - nM);
                Mx[i][rh] = nM;
                float ls = 0.f;
                #pragma unroll
                for (int j = 0; j < 8; j++) {
                    uint32_t pe = h2exp2(pk(s[i][j][2 * rh] - nM,
                                            s[i][j][2 * rh + 1] - nM));
                    P[i][rh][j] = pe;
                    float2 f = __half22float2(*(__half2*)&pe);
                    ls += f.x + f.y;
                }
                ls += __shfl_xor_sync(0xffffffffu, ls, 1);
                ls += __shfl_xor_sync(0xffffffffu, ls, 2);
                L[i][rh] = L[i][rh] * corr + ls;
                #pragma unroll
                for (int j = 0; j < 8; j++) {
                    o[i][j][2 * rh]     *= corr;
                    o[i][j][2 * rh + 1] *= corr;
                }
            }
        }

        // ---- O += P * V^T ----
        #pragma unroll
        for (int ms2 = 0; ms2 < 4; ms2++) {
            uint32_t aP[2][4];
            #pragma unroll
            for (int i = 0; i < 2; i++) {
                aP[i][0] = P[i][0][2 * ms2];
                aP[i][1] = P[i][1][2 * ms2];
                aP[i][2] = P[i][0][2 * ms2 + 1];
                aP[i][3] = P[i][1][2 * ms2 + 1];
            }
            #pragma unroll
            for (int jj = 0; jj < 4; jj++) {
                uint32_t bf[4];
                ldsm4(bf, vAddr + jj * 16 * LDK * 2 + ms2 * 32);
                mma16816(o[0][2 * jj],     aP[0], bf[0], bf[1]);
                mma16816(o[0][2 * jj + 1], aP[0], bf[2], bf[3]);
                mma16816(o[1][2 * jj],     aP[1], bf[0], bf[1]);
                mma16816(o[1][2 * jj + 1], aP[1], bf[2], bf[3]);
            }
        }
        __syncthreads();
    }

    // ---- epilogue: smem transpose -> coalesced fp16 stores ----
    __half* os = smh;
    #pragma unroll
    for (int i = 0; i < 2; i++) {
        float inv0 = 1.f / L[i][0];
        float inv1 = 1.f / L[i][1];
        int rl = rowbase + 16 * i + g;
        #pragma unroll
        for (int j = 0; j < 8; j++) {
            int d = 8 * j + 2 * t;
            *(uint32_t*)&os[rl * LDO + d]       = pk(o[i][j][0] * inv0, o[i][j][1] * inv0);
            *(uint32_t*)&os[(rl + 8) * LDO + d] = pk(o[i][j][2] * inv1, o[i][j][3] * inv1);
        }
    }
    __syncthreads();
    {
        const int d = tid >> 1, seg = (tid & 1) * 64;
        __half* dst = outh + ((size_t)b * CH + h * HD + d) * NN + n0 + seg;
        #pragma unroll
        for (int c8 = 0; c8 < 8; c8++) {
            __half tmp[8];
            #pragma unroll
            for (int r = 0; r < 8; r++)
                tmp[r] = os[(seg + c8 * 8 + r) * LDO + d];
            *(uint4*)&dst[c8 * 8] = *(uint4*)tmp;
        }
    }
}

// ---------------------------------------------------------------------------
// GroupNorm two-pass over fp16 proj (unchanged)
// ---------------------------------------------------------------------------
__global__ __launch_bounds__(256) void gn_stat(const __half* __restrict__ p)
{
    const int bg = blockIdx.x >> 3, sp = blockIdx.x & 7;
    const uint4* p8 = (const uint4*)(p + (size_t)bg * CPG * NN) + sp * 1024;
    float sum = 0.f, ss = 0.f;
    #pragma unroll
    for (int it = 0; it < 4; it++) {
        uint4 u = p8[threadIdx.x + it * 256];
        const __half2* hp = (const __half2*)&u;
        #pragma unroll
        for (int j = 0; j < 4; j++) {
            float2 f = __half22float2(hp[j]);
            sum += f.x + f.y;
            ss  += f.x * f.x + f.y * f.y;
        }
    }
    #pragma unroll
    for (int off = 16; off; off >>= 1) {
        sum += __shfl_xor_sync(0xffffffffu, sum, off);
        ss  += __shfl_xor_sync(0xffffffffu, ss, off);
    }
    __shared__ float rs[8], rq[8];
    const int warp = threadIdx.x >> 5;
    if ((threadIdx.x & 31) == 0) { rs[warp] = sum; rq[warp] = ss; }
    __syncthreads();
    if (threadIdx.x == 0) {
        float s = 0.f, q = 0.f;
        #pragma unroll
        for (int w = 0; w < 8; w++) { s += rs[w]; q += rq[w]; }
        g_part[blockIdx.x * 2]     = s;
        g_part[blockIdx.x * 2 + 1] = q;
    }
}

__global__ __launch_bounds__(256) void gn_apply(
    const __half* __restrict__ p, const float* __restrict__ x,
    const float* __restrict__ gamma, const float* __restrict__ beta,
    float* __restrict__ out)
{
    const int bg = blockIdx.x >> 3, sp = blockIdx.x & 7;
    float sum = 0.f, ss = 0.f;
    #pragma unroll
    for (int i = 0; i < 8; i++) {
        sum += g_part[(bg * 8 + i) * 2];
        ss  += g_part[(bg * 8 + i) * 2 + 1];
    }
    const float invn = 1.f / 65536.f;
    const float mean = sum * invn;
    const float inv  = rsqrtf(ss * invn - mean * mean + GN_EPS);
    const int grp = bg & 7;

    const size_t base = (size_t)bg * CPG * NN;
    const uint4*  p8 = (const uint4*)(p + base) + sp * 1024;
    const float4* x4 = (const float4*)(x + base) + sp * 2048;
    float4*       o4 = (float4*)(out + base) + sp * 2048;

    #pragma unroll
    for (int it = 0; it < 4; it++) {
        int idx = threadIdx.x + it * 256;
        int c = grp * CPG + sp * 8 + (idx >> 7);
        float ga = gamma[c] * inv, be = beta[c];
        uint4 u = p8[idx];
        const __half2* hp = (const __half2*)&u;
        float4 xa = x4[2 * idx], xb = x4[2 * idx + 1];
        float2 f0 = __half22float2(hp[0]), f1 = __half22float2(hp[1]);
        float2 f2 = __half22float2(hp[2]), f3 = __half22float2(hp[3]);
        float4 ra, rb;
        ra.x = (f0.x - mean) * ga + be + xa.x;
        ra.y = (f0.y - mean) * ga + be + xa.y;
        ra.z = (f1.x - mean) * ga + be + xa.z;
        ra.w = (f1.y - mean) * ga + be + xa.w;
        rb.x = (f2.x - mean) * ga + be + xb.x;
        rb.y = (f2.y - mean) * ga + be + xb.y;
        rb.z = (f3.x - mean) * ga + be + xb.z;
        rb.w = (f3.y - mean) * ga + be + xb.w;
        o4[2 * idx]     = ra;
        o4[2 * idx + 1] = rb;
    }
}

// ---------------------------------------------------------------------------
extern "C" void kernel_launch(void* const* d_in, const int* in_sizes, int n_in,
                              void* d_out, int out_size)
{
    const float* x      = (const float*)d_in[0];
    const float* w_qkv  = (const float*)d_in[1];
    const float* w_proj = (const float*)d_in[2];
    const float* gamma  = (const float*)d_in[3];
    const float* beta   = (const float*)d_in[4];
    float* out = (float*)d_out;

    __half *w16, *wp16, *x16, *qkvh, *atth, *projh;
    cudaGetSymbolAddress((void**)&w16,   g_w16);
    cudaGetSymbolAddress((void**)&wp16,  g_wp16);
    cudaGetSymbolAddress((void**)&x16,   g_x16);
    cudaGetSymbolAddress((void**)&qkvh,  g_qkvh);
    cudaGetSymbolAddress((void**)&atth,  g_atth);
    cudaGetSymbolAddress((void**)&projh, g_projh);

    static bool attr_set = false;
    if (!attr_set) {
        cudaFuncSetAttribute(attn_h,
            cudaFuncAttributeMaxDynamicSharedMemorySize, ATT_SMEM);
        cudaFuncSetAttribute((const void*)gemm_a<__half, true, 4>,
            cudaFuncAttributeMaxDynamicSharedMemorySize, GCfg<4>::SMEM);
        cudaFuncSetAttribute((const void*)gemm_a<__half, false, 2>,
            cudaFuncAttributeMaxDynamicSharedMemorySize, GCfg<2>::SMEM);
        attr_set = true;
    }

    // 0) single-launch fp32 -> fp16 conversion
    cvt_all<<<1280, 256>>>(w_qkv, w16, w_proj, wp16, x, x16);

    // 1) QKV projection (Q rows scaled by 0.125*log2e), 256x128 tiles
    gemm_a<__half, true, 4><<<dim3(NN / 128, (3 * CH) / 256, BATCH), 256,
                              GCfg<4>::SMEM>>>(w16, x16, qkvh, 3 * CH, NN, CH);

    // 2) Fused flash attention (128-row tiles, f16x2 softmax)
    attn_h<<<dim3(NN / 128, NH, BATCH), 128, ATT_SMEM>>>(qkvh, atth);

    // 3) Output projection -> fp16, 128x128 tiles (grid 256, latency fix)
    gemm_a<__half, false, 2><<<dim3(NN / 128, CH / 128, BATCH), 256,
                               GCfg<2>::SMEM>>>(wp16, atth, projh, CH, NN, CH);

    // 4) GroupNorm + affine + residual
    gn_stat<<<512, 256>>>(projh);
    gn_apply<<<512, 256>>>(projh, x, gamma, beta, out);
}

// round 12
// speedup vs baseline: 1.0467x; 1.0337x over previous
#include <cuda_runtime.h>
#include <cuda_fp16.h>
#include <math.h>
#include <stdint.h>

#define BATCH 8
#define CH    512
#define NN    1024
#define NH    8
#define HD    64
#define CPG   64
#define GN_EPS 1e-5f

// fp16 scratch
__device__ __half g_w16[(size_t)3 * CH * CH];
__device__ __half g_wp16[(size_t)CH * CH];
__device__ __half g_x16[(size_t)BATCH * CH * NN];
__device__ __half g_qkvh[(size_t)BATCH * 3 * CH * NN];
__device__ __half g_atth[(size_t)BATCH * CH * NN];
__device__ __half g_projh[(size_t)BATCH * CH * NN];
__device__ float  g_gnp[BATCH * 8 * 8 * 2];   // [b*8+grp][xblk][{sum,ss}]

// ---------------------------------------------------------------------------
// helpers
// ---------------------------------------------------------------------------
__device__ __forceinline__ uint32_t smem_u32(const void* p) {
    uint32_t a;
    asm("{ .reg .u64 t; cvta.to.shared.u64 t, %1; cvt.u32.u64 %0, t; }" : "=r"(a) : "l"(p));
    return a;
}
__device__ __forceinline__ uint32_t pk(float x, float y) {
    __half2 h = __floats2half2_rn(x, y);
    return *(uint32_t*)&h;
}
__device__ __forceinline__ void mma16816(float* c, const uint32_t* a,
                                         uint32_t b0, uint32_t b1) {
    asm volatile(
        "mma.sync.aligned.m16n8k16.row.col.f32.f16.f16.f32 "
        "{%0,%1,%2,%3},{%4,%5,%6,%7},{%8,%9},{%0,%1,%2,%3};"
        : "+f"(c[0]), "+f"(c[1]), "+f"(c[2]), "+f"(c[3])
        : "r"(a[0]), "r"(a[1]), "r"(a[2]), "r"(a[3]), "r"(b0), "r"(b1));
}
__device__ __forceinline__ void ldsm4(uint32_t* r, uint32_t addr) {
    asm volatile("ldmatrix.sync.aligned.m8n8.x4.shared.b16 {%0,%1,%2,%3}, [%4];"
        : "=r"(r[0]), "=r"(r[1]), "=r"(r[2]), "=r"(r[3]) : "r"(addr));
}
__device__ __forceinline__ void ldsm4t(uint32_t* r, uint32_t addr) {
    asm volatile("ldmatrix.sync.aligned.m8n8.x4.trans.shared.b16 {%0,%1,%2,%3}, [%4];"
        : "=r"(r[0]), "=r"(r[1]), "=r"(r[2]), "=r"(r[3]) : "r"(addr));
}
__device__ __forceinline__ void cp_async16(uint32_t dst, const void* src) {
    asm volatile("cp.async.ca.shared.global [%0], [%1], 16;" :: "r"(dst), "l"(src));
}
#define CP_COMMIT() asm volatile("cp.async.commit_group;" ::: "memory")
#define CP_WAIT(n)  asm volatile("cp.async.wait_group %0;" :: "n"(n) : "memory")

// ---------------------------------------------------------------------------
// single-launch fp32 -> fp16 conversion
// ---------------------------------------------------------------------------
#define CVT_N1 ((3 * CH * CH) / 4)
#define CVT_N2 ((CH * CH) / 4)
#define CVT_N3 ((BATCH * CH * NN) / 4)
__global__ __launch_bounds__(256) void cvt_all(
    const float* __restrict__ w, __half* __restrict__ w16,
    const float* __restrict__ wp, __half* __restrict__ wp16,
    const float* __restrict__ x, __half* __restrict__ x16)
{
    const int total = CVT_N1 + CVT_N2 + CVT_N3;
    for (int i = blockIdx.x * 256 + threadIdx.x; i < total; i += gridDim.x * 256) {
        const float* s; __half* d; int j;
        if (i < CVT_N1)                { s = w;  d = w16;  j = i; }
        else if (i < CVT_N1 + CVT_N2)  { s = wp; d = wp16; j = i - CVT_N1; }
        else                           { s = x;  d = x16;  j = i - CVT_N1 - CVT_N2; }
        float4 v = *(const float4*)&s[(size_t)j * 4];
        *(uint2*)&d[(size_t)j * 4] = make_uint2(pk(v.x, v.y), pk(v.z, v.w));
    }
}

// ---------------------------------------------------------------------------
// all-fp16 cp.async 3-stage GEMM. CTA 256x128, 8 warps (4x2),
// warp tile 64x64, k-tile 32. GNP: emit GroupNorm partial sums (proj).
// ---------------------------------------------------------------------------
#define LDA 40
#define LDB 136
#define STG_A (256 * LDA)
#define STG_B (32 * LDB)
#define STG_H (STG_A + STG_B)
#define GSMEM (3 * STG_H * 2)

template<typename TC, bool SCALEQ, bool GNP>
__global__ __launch_bounds__(256) void gemm_a(
    const __half* __restrict__ A, const __half* __restrict__ Bg,
    TC* __restrict__ Cg, int M, int N, int K)
{
    extern __shared__ __half sh[];

    const int bz = blockIdx.z;
    const __half* Bp = Bg + (size_t)bz * K * N;
    TC*           Cp = Cg + (size_t)bz * M * N;

    const int tid = threadIdx.x;
    const int warp = tid >> 5, lane = tid & 31;
    const int wm = warp >> 1, wn = warp & 1;
    const int g = lane >> 2, t = lane & 3;
    const int row0 = blockIdx.y * 256;
    const int col0 = blockIdx.x * 128;
    const uint32_t sb = smem_u32(sh);
    const int nk = K / 32;

    auto issue = [&](int kt, int st) {
        const uint32_t sau = sb + st * STG_H * 2;
        const uint32_t sbu = sau + STG_A * 2;
        #pragma unroll
        for (int i = 0; i < 4; i++) {
            int idx = tid + i * 256;
            int r = idx >> 2, ch = idx & 3;
            cp_async16(sau + (r * LDA + ch * 8) * 2,
                       A + (size_t)(row0 + r) * K + kt * 32 + ch * 8);
        }
        #pragma unroll
        for (int i = 0; i < 2; i++) {
            int idx = tid + i * 256;
            int r = idx >> 4, ch = idx & 15;
            cp_async16(sbu + (r * LDB + ch * 8) * 2,
                       Bp + (size_t)(kt * 32 + r) * N + col0 + ch * 8);
        }
        CP_COMMIT();
    };

    float acc[4][8][4];
    #pragma unroll
    for (int i = 0; i < 4; i++)
        #pragma unroll
        for (int j = 0; j < 8; j++)
            #pragma unroll
            for (int e = 0; e < 4; e++) acc[i][j][e] = 0.f;

    issue(0, 0);
    issue(1, 1);

    const uint32_t aLane = (((wm * 64 + (lane & 15)) * LDA) + 8 * (lane >> 4)) * 2;
    const uint32_t bLane = ((((lane & 7) + 8 * ((lane >> 3) & 1)) * LDB)
                            + wn * 64 + 8 * (lane >> 4)) * 2;

    for (int kt = 0; kt < nk; kt++) {
        const int st = kt % 3;
        if (kt + 1 < nk) { CP_WAIT(1); } else { CP_WAIT(0); }
        __syncthreads();
        if (kt + 2 < nk) issue(kt + 2, (kt + 2) % 3);

        const uint32_t aAddr = sb + st * STG_H * 2 + aLane;
        const uint32_t bAddr = sb + st * STG_H * 2 + STG_A * 2 + bLane;
        #pragma unroll
        for (int ks = 0; ks < 2; ks++) {
            uint32_t a[4][4];
            #pragma unroll
            for (int mi = 0; mi < 4; mi++)
                ldsm4(a[mi], aAddr + ks * 32 + mi * 16 * LDA * 2);
            #pragma unroll
            for (int jj = 0; jj < 4; jj++) {
                uint32_t b[4];
                ldsm4t(b, bAddr + ks * 16 * LDB * 2 + jj * 32);
                #pragma unroll
                for (int mi = 0; mi < 4; mi++) {
                    mma16816(acc[mi][2 * jj],     a[mi], b[0], b[1]);
                    mma16816(acc[mi][2 * jj + 1], a[mi], b[2], b[3]);
                }
            }
        }
    }

    const float cs = (SCALEQ && row0 < 512) ? 0.125f * 1.44269504f : 1.f;
    #pragma unroll
    for (int mi = 0; mi < 4; mi++) {
        int r = row0 + wm * 64 + mi * 16 + g;
        #pragma unroll
        for (int j = 0; j < 8; j++) {
            int c = col0 + wn * 64 + 8 * j + 2 * t;
            if constexpr (sizeof(TC) == 2) {
                *(uint32_t*)&Cp[(size_t)r * N + c] =
                    pk(acc[mi][j][0] * cs, acc[mi][j][1] * cs);
                *(uint32_t*)&Cp[(size_t)(r + 8) * N + c] =
                    pk(acc[mi][j][2] * cs, acc[mi][j][3] * cs);
            } else {
                *(float2*)&Cp[(size_t)r * N + c] =
                    make_float2(acc[mi][j][0] * cs, acc[mi][j][1] * cs);
                *(float2*)&Cp[(size_t)(r + 8) * N + c] =
                    make_float2(acc[mi][j][2] * cs, acc[mi][j][3] * cs);
            }
        }
    }

    // ---- GroupNorm partial sums (proj only): warp slice = one 64-row group ----
    if constexpr (GNP) {
        float sum = 0.f, ss = 0.f;
        #pragma unroll
        for (int mi = 0; mi < 4; mi++)
            #pragma unroll
            for (int j = 0; j < 8; j++)
                #pragma unroll
                for (int e = 0; e < 4; e++) {
                    float v = acc[mi][j][e];
                    sum += v;
                    ss  += v * v;
                }
        #pragma unroll
        for (int off = 16; off; off >>= 1) {
            sum += __shfl_xor_sync(0xffffffffu, sum, off);
            ss  += __shfl_xor_sync(0xffffffffu, ss, off);
        }
        __syncthreads();                    // mainloop smem fully consumed
        float* red = (float*)sh;
        if (lane == 0) { red[warp * 2] = sum; red[warp * 2 + 1] = ss; }
        __syncthreads();
        if (tid < 4) {                      // tid == wm: one group per wm
            float s = red[(tid * 2) * 2]     + red[(tid * 2 + 1) * 2];
            float q = red[(tid * 2) * 2 + 1] + red[(tid * 2 + 1) * 2 + 1];
            int grp = (row0 >> 6) + tid;
            g_gnp[((bz * 8 + grp) * 8 + blockIdx.x) * 2]     = s;
            g_gnp[((bz * 8 + grp) * 8 + blockIdx.x) * 2 + 1] = q;
        }
    }
}

// ---------------------------------------------------------------------------
// Fused flash attention (R8 config: 128 rows, 4 warps, exp2f softmax)
// ---------------------------------------------------------------------------
#define LDQ 136
#define LDK 72
#define LDO 72
#define ATT_SMEM ((64 * LDQ + 4 * 64 * LDK) * 2)

__global__ __launch_bounds__(128) void attn_h(
    const __half* __restrict__ qkv, __half* __restrict__ outh)
{
    extern __shared__ __half smh[];
    __half* qs = smh;
    __half* kv = smh + 64 * LDQ;

    const int b = blockIdx.z, h = blockIdx.y;
    const int n0 = blockIdx.x * 128;
    const int tid = threadIdx.x, warp = tid >> 5, lane = tid & 31;
    const int g = lane >> 2, t = lane & 3;
    const int rowbase = warp * 32;

    const __half* q = qkv + (((size_t)b * 3 + 0) * NH + h) * HD * NN;
    const __half* k = qkv + (((size_t)b * 3 + 1) * NH + h) * HD * NN;
    const __half* v = qkv + (((size_t)b * 3 + 2) * NH + h) * HD * NN;

    const uint32_t qb  = smem_u32(qs);
    const uint32_t kvb = smem_u32(kv);
    const uint32_t qLane = ((((lane & 7) + 8 * (lane >> 4)) * LDQ)
                            + rowbase + 8 * ((lane >> 3) & 1)) * 2;
    const uint32_t kLane = ((((lane & 7) + 8 * ((lane >> 3) & 1)) * LDK)
                            + 8 * (lane >> 4)) * 2;
    const uint32_t vLane = ((((lane & 7) + 8 * (lane >> 4)) * LDK)
                            + 8 * ((lane >> 3) & 1)) * 2;

    auto issueKV = [&](int mt, int st) {
        const int m0 = mt * 64;
        const uint32_t kd = kvb + st * (2 * 64 * LDK) * 2;
        const uint32_t vd = kd + (64 * LDK) * 2;
        #pragma unroll
        for (int i = 0; i < 4; i++) {
            int idx = tid + i * 128;
            int d = idx >> 3, ch = idx & 7;
            cp_async16(kd + (d * LDK + ch * 8) * 2, k + (size_t)d * NN + m0 + ch * 8);
            cp_async16(vd + (d * LDK + ch * 8) * 2, v + (size_t)d * NN + m0 + ch * 8);
        }
    };

    #pragma unroll
    for (int i = 0; i < 8; i++) {
        int idx = tid + i * 128;
        int d = idx >> 4, ch = idx & 15;
        cp_async16(qb + (d * LDQ + ch * 8) * 2, q + (size_t)d * NN + n0 + ch * 8);
    }
    issueKV(0, 0);
    CP_COMMIT();

    float o[2][8][4];
    float Mx[2][2], L[2][2];
    #pragma unroll
    for (int i = 0; i < 2; i++) {
        #pragma unroll
        for (int j = 0; j < 8; j++)
            #pragma unroll
            for (int e = 0; e < 4; e++) o[i][j][e] = 0.f;
        Mx[i][0] = Mx[i][1] = -1e30f;
        L[i][0] = L[i][1] = 0.f;
    }

    for (int mt = 0; mt < NN / 64; mt++) {
        const int st = mt & 1;
        if (mt + 1 < NN / 64) {
            issueKV(mt + 1, st ^ 1);
            CP_COMMIT();
            CP_WAIT(1);
        } else {
            CP_WAIT(0);
        }
        __syncthreads();

        const uint32_t kAddr = kvb + st * (2 * 64 * LDK) * 2 + kLane;
        const uint32_t vAddr = kvb + st * (2 * 64 * LDK) * 2 + (64 * LDK) * 2 + vLane;

        float s[2][8][4];
        #pragma unroll
        for (int i = 0; i < 2; i++)
            #pragma unroll
            for (int j = 0; j < 8; j++)
                #pragma unroll
                for (int e = 0; e < 4; e++) s[i][j][e] = 0.f;

        #pragma unroll
        for (int ks16 = 0; ks16 < 4; ks16++) {
            uint32_t a[2][4];
            ldsm4t(a[0], qb + qLane + ks16 * 16 * LDQ * 2);
            ldsm4t(a[1], qb + qLane + ks16 * 16 * LDQ * 2 + 32);
            #pragma unroll
            for (int jj = 0; jj < 4; jj++) {
                uint32_t bf[4];
                ldsm4t(bf, kAddr + ks16 * 16 * LDK * 2 + jj * 32);
                mma16816(s[0][2 * jj],     a[0], bf[0], bf[1]);
                mma16816(s[0][2 * jj + 1], a[0], bf[2], bf[3]);
                mma16816(s[1][2 * jj],     a[1], bf[0], bf[1]);
                mma16816(s[1][2 * jj + 1], a[1], bf[2], bf[3]);
            }
        }

        #pragma unroll
        for (int i = 0; i < 2; i++) {
            #pragma unroll
            for (int rh = 0; rh < 2; rh++) {
                float tm = -1e30f;
                #pragma unroll
                for (int j = 0; j < 8; j++)
                    tm = fmaxf(tm, fmaxf(s[i][j][2 * rh], s[i][j][2 * rh + 1]));
                tm = fmaxf(tm, __shfl_xor_sync(0xffffffffu, tm, 1));
                tm = fmaxf(tm, __shfl_xor_sync(0xffffffffu, tm, 2));
                float nM = fmaxf(Mx[i][rh], tm);
                float corr = exp2f(Mx[i][rh] - nM);
                Mx[i][rh] = nM;
                float ls = 0.f;
                #pragma unroll
                for (int j = 0; j < 8; j++) {
                    float p0 = exp2f(s[i][j][2 * rh] - nM);
                    float p1 = exp2f(s[i][j][2 * rh + 1] - nM);
                    s[i][j][2 * rh] = p0;
                    s[i][j][2 * rh + 1] = p1;
                    ls += p0 + p1;
                }
                ls += __shfl_xor_sync(0xffffffffu, ls, 1);
                ls += __shfl_xor_sync(0xffffffffu, ls, 2);
                L[i][rh] = L[i][rh] * corr + ls;
                #pragma unroll
                for (int j = 0; j < 8; j++) {
                    o[i][j][2 * rh]     *= corr;
                    o[i][j][2 * rh + 1] *= corr;
                }
            }
        }

        #pragma unroll
        for (int ms2 = 0; ms2 < 4; ms2++) {
            uint32_t aP[2][4];
            #pragma unroll
            for (int i = 0; i < 2; i++) {
                aP[i][0] = pk(s[i][2 * ms2][0],     s[i][2 * ms2][1]);
                aP[i][1] = pk(s[i][2 * ms2][2],     s[i][2 * ms2][3]);
                aP[i][2] = pk(s[i][2 * ms2 + 1][0], s[i][2 * ms2 + 1][1]);
                aP[i][3] = pk(s[i][2 * ms2 + 1][2], s[i][2 * ms2 + 1][3]);
            }
            #pragma unroll
            for (int jj = 0; jj < 4; jj++) {
                uint32_t bf[4];
                ldsm4(bf, vAddr + jj * 16 * LDK * 2 + ms2 * 32);
                mma16816(o[0][2 * jj],     aP[0], bf[0], bf[1]);
                mma16816(o[0][2 * jj + 1], aP[0], bf[2], bf[3]);
                mma16816(o[1][2 * jj],     aP[1], bf[0], bf[1]);
                mma16816(o[1][2 * jj + 1], aP[1], bf[2], bf[3]);
            }
        }
        __syncthreads();
    }

    __half* os = smh;
    #pragma unroll
    for (int i = 0; i < 2; i++) {
        float inv0 = 1.f / L[i][0];
        float inv1 = 1.f / L[i][1];
        int rl = rowbase + 16 * i + g;
        #pragma unroll
        for (int j = 0; j < 8; j++) {
            int d = 8 * j + 2 * t;
            *(uint32_t*)&os[rl * LDO + d]       = pk(o[i][j][0] * inv0, o[i][j][1] * inv0);
            *(uint32_t*)&os[(rl + 8) * LDO + d] = pk(o[i][j][2] * inv1, o[i][j][3] * inv1);
        }
    }
    __syncthreads();
    {
        const int d = tid >> 1, seg = (tid & 1) * 64;
        __half* dst = outh + ((size_t)b * CH + h * HD + d) * NN + n0 + seg;
        #pragma unroll
        for (int c8 = 0; c8 < 8; c8++) {
            __half tmp[8];
            #pragma unroll
            for (int r = 0; r < 8; r++)
                tmp[r] = os[(seg + c8 * 8 + r) * LDO + d];
            *(uint4*)&dst[c8 * 8] = *(uint4*)tmp;
        }
    }
}

// ---------------------------------------------------------------------------
// GroupNorm apply (stats from GEMM-epilogue partials) + residual
// ---------------------------------------------------------------------------
__global__ __launch_bounds__(256) void gn_apply(
    const __half* __restrict__ p, const float* __restrict__ x,
    const float* __restrict__ gamma, const float* __restrict__ beta,
    float* __restrict__ out)
{
    const int bg = blockIdx.x >> 3, sp = blockIdx.x & 7;
    float sum = 0.f, ss = 0.f;
    #pragma unroll
    for (int xk = 0; xk < 8; xk++) {
        sum += g_gnp[(bg * 8 + xk) * 2];
        ss  += g_gnp[(bg * 8 + xk) * 2 + 1];
    }
    const float invn = 1.f / 65536.f;
    const float mean = sum * invn;
    const float inv  = rsqrtf(ss * invn - mean * mean + GN_EPS);
    const int grp = bg & 7;

    const size_t base = (size_t)bg * CPG * NN;
    const uint4*  p8 = (const uint4*)(p + base) + sp * 1024;
    const float4* x4 = (const float4*)(x + base) + sp * 2048;
    float4*       o4 = (float4*)(out + base) + sp * 2048;

    #pragma unroll
    for (int it = 0; it < 4; it++) {
        int idx = threadIdx.x + it * 256;
        int c = grp * CPG + sp * 8 + (idx >> 7);
        float ga = gamma[c] * inv, be = beta[c];
        uint4 u = p8[idx];
        const __half2* hp = (const __half2*)&u;
        float4 xa = x4[2 * idx], xb = x4[2 * idx + 1];
        float2 f0 = __half22float2(hp[0]), f1 = __half22float2(hp[1]);
        float2 f2 = __half22float2(hp[2]), f3 = __half22float2(hp[3]);
        float4 ra, rb;
        ra.x = (f0.x - mean) * ga + be + xa.x;
        ra.y = (f0.y - mean) * ga + be + xa.y;
        ra.z = (f1.x - mean) * ga + be + xa.z;
        ra.w = (f1.y - mean) * ga + be + xa.w;
        rb.x = (f2.x - mean) * ga + be + xb.x;
        rb.y = (f2.y - mean) * ga + be + xb.y;
        rb.z = (f3.x - mean) * ga + be + xb.z;
        rb.w = (f3.y - mean) * ga + be + xb.w;
        o4[2 * idx]     = ra;
        o4[2 * idx + 1] = rb;
    }
}

// ---------------------------------------------------------------------------
extern "C" void kernel_launch(void* const* d_in, const int* in_sizes, int n_in,
                              void* d_out, int out_size)
{
    const float* x      = (const float*)d_in[0];
    const float* w_qkv  = (const float*)d_in[1];
    const float* w_proj = (const float*)d_in[2];
    const float* gamma  = (const float*)d_in[3];
    const float* beta   = (const float*)d_in[4];
    float* out = (float*)d_out;

    __half *w16, *wp16, *x16, *qkvh, *atth, *projh;
    cudaGetSymbolAddress((void**)&w16,   g_w16);
    cudaGetSymbolAddress((void**)&wp16,  g_wp16);
    cudaGetSymbolAddress((void**)&x16,   g_x16);
    cudaGetSymbolAddress((void**)&qkvh,  g_qkvh);
    cudaGetSymbolAddress((void**)&atth,  g_atth);
    cudaGetSymbolAddress((void**)&projh, g_projh);

    static bool attr_set = false;
    if (!attr_set) {
        cudaFuncSetAttribute(attn_h,
            cudaFuncAttributeMaxDynamicSharedMemorySize, ATT_SMEM);
        cudaFuncSetAttribute((const void*)gemm_a<__half, true, false>,
            cudaFuncAttributeMaxDynamicSharedMemorySize, GSMEM);
        cudaFuncSetAttribute((const void*)gemm_a<__half, false, true>,
            cudaFuncAttributeMaxDynamicSharedMemorySize, GSMEM);
        attr_set = true;
    }

    // 0) single-launch fp32 -> fp16 conversion
    cvt_all<<<1280, 256>>>(w_qkv, w16, w_proj, wp16, x, x16);

    // 1) QKV projection (Q rows scaled by 0.125*log2e), 256x128 tiles
    gemm_a<__half, true, false><<<dim3(NN / 128, (3 * CH) / 256, BATCH), 256, GSMEM>>>(
        w16, x16, qkvh, 3 * CH, NN, CH);

    // 2) Fused flash attention
    attn_h<<<dim3(NN / 128, NH, BATCH), 128, ATT_SMEM>>>(qkvh, atth);

    // 3) Output projection -> fp16, GN partials fused into epilogue
    gemm_a<__half, false, true><<<dim3(NN / 128, CH / 256, BATCH), 256, GSMEM>>>(
        wp16, atth, projh, CH, NN, CH);

    // 4) GroupNorm apply + residual (stats from fused partials)
    gn_apply<<<512, 256>>>(projh, x, gamma, beta, out);
}

// round 13
// speedup vs baseline: 1.0510x; 1.0042x over previous
#include <cuda_runtime.h>
#include <cuda_fp16.h>
#include <math.h>
#include <stdint.h>

#define BATCH 8
#define CH    512
#define NN    1024
#define NH    8
#define HD    64
#define CPG   64
#define GN_EPS 1e-5f

// fp16 scratch
__device__ __half g_w16[(size_t)3 * CH * CH];
__device__ __half g_wp16[(size_t)CH * CH];
__device__ __half g_x16[(size_t)BATCH * CH * NN];
__device__ __half g_qkvh[(size_t)BATCH * 3 * CH * NN];
__device__ __half g_atth[(size_t)BATCH * CH * NN];
__device__ __half g_projh[(size_t)BATCH * CH * NN];
__device__ float  g_gnp[BATCH * 8 * 8 * 2];   // [b*8+grp][xblk][{sum,ss}]

// ---------------------------------------------------------------------------
// helpers
// ---------------------------------------------------------------------------
__device__ __forceinline__ uint32_t smem_u32(const void* p) {
    uint32_t a;
    asm("{ .reg .u64 t; cvta.to.shared.u64 t, %1; cvt.u32.u64 %0, t; }" : "=r"(a) : "l"(p));
    return a;
}
__device__ __forceinline__ uint32_t pk(float x, float y) {
    __half2 h = __floats2half2_rn(x, y);
    return *(uint32_t*)&h;
}
__device__ __forceinline__ void mma16816(float* c, const uint32_t* a,
                                         uint32_t b0, uint32_t b1) {
    asm volatile(
        "mma.sync.aligned.m16n8k16.row.col.f32.f16.f16.f32 "
        "{%0,%1,%2,%3},{%4,%5,%6,%7},{%8,%9},{%0,%1,%2,%3};"
        : "+f"(c[0]), "+f"(c[1]), "+f"(c[2]), "+f"(c[3])
        : "r"(a[0]), "r"(a[1]), "r"(a[2]), "r"(a[3]), "r"(b0), "r"(b1));
}
__device__ __forceinline__ void ldsm4(uint32_t* r, uint32_t addr) {
    asm volatile("ldmatrix.sync.aligned.m8n8.x4.shared.b16 {%0,%1,%2,%3}, [%4];"
        : "=r"(r[0]), "=r"(r[1]), "=r"(r[2]), "=r"(r[3]) : "r"(addr));
}
__device__ __forceinline__ void ldsm4t(uint32_t* r, uint32_t addr) {
    asm volatile("ldmatrix.sync.aligned.m8n8.x4.trans.shared.b16 {%0,%1,%2,%3}, [%4];"
        : "=r"(r[0]), "=r"(r[1]), "=r"(r[2]), "=r"(r[3]) : "r"(addr));
}
__device__ __forceinline__ void cp_async16(uint32_t dst, const void* src) {
    asm volatile("cp.async.ca.shared.global [%0], [%1], 16;" :: "r"(dst), "l"(src));
}
#define CP_COMMIT() asm volatile("cp.async.commit_group;" ::: "memory")
#define CP_WAIT(n)  asm volatile("cp.async.wait_group %0;" :: "n"(n) : "memory")

// ---------------------------------------------------------------------------
// single-launch fp32 -> fp16 conversion
// ---------------------------------------------------------------------------
#define CVT_N1 ((3 * CH * CH) / 4)
#define CVT_N2 ((CH * CH) / 4)
#define CVT_N3 ((BATCH * CH * NN) / 4)
__global__ __launch_bounds__(256) void cvt_all(
    const float* __restrict__ w, __half* __restrict__ w16,
    const float* __restrict__ wp, __half* __restrict__ wp16,
    const float* __restrict__ x, __half* __restrict__ x16)
{
    const int total = CVT_N1 + CVT_N2 + CVT_N3;
    for (int i = blockIdx.x * 256 + threadIdx.x; i < total; i += gridDim.x * 256) {
        const float* s; __half* d; int j;
        if (i < CVT_N1)                { s = w;  d = w16;  j = i; }
        else if (i < CVT_N1 + CVT_N2)  { s = wp; d = wp16; j = i - CVT_N1; }
        else                           { s = x;  d = x16;  j = i - CVT_N1 - CVT_N2; }
        float4 v = *(const float4*)&s[(size_t)j * 4];
        *(uint2*)&d[(size_t)j * 4] = make_uint2(pk(v.x, v.y), pk(v.z, v.w));
    }
}

// ---------------------------------------------------------------------------
// all-fp16 cp.async 3-stage GEMM. CTA 256x128, 8 warps (4x2),
// warp tile 64x64, k-tile 32. GNP: emit GroupNorm partial sums (proj).
// ---------------------------------------------------------------------------
#define LDA 40
#define LDB 136
#define STG_A (256 * LDA)
#define STG_B (32 * LDB)
#define STG_H (STG_A + STG_B)
#define GSMEM (3 * STG_H * 2)

template<typename TC, bool SCALEQ, bool GNP>
__global__ __launch_bounds__(256) void gemm_a(
    const __half* __restrict__ A, const __half* __restrict__ Bg,
    TC* __restrict__ Cg, int M, int N, int K)
{
    extern __shared__ __half sh[];

    const int bz = blockIdx.z;
    const __half* Bp = Bg + (size_t)bz * K * N;
    TC*           Cp = Cg + (size_t)bz * M * N;

    const int tid = threadIdx.x;
    const int warp = tid >> 5, lane = tid & 31;
    const int wm = warp >> 1, wn = warp & 1;
    const int g = lane >> 2, t = lane & 3;
    const int row0 = blockIdx.y * 256;
    const int col0 = blockIdx.x * 128;
    const uint32_t sb = smem_u32(sh);
    const int nk = K / 32;

    auto issue = [&](int kt, int st) {
        const uint32_t sau = sb + st * STG_H * 2;
        const uint32_t sbu = sau + STG_A * 2;
        #pragma unroll
        for (int i = 0; i < 4; i++) {
            int idx = tid + i * 256;
            int r = idx >> 2, ch = idx & 3;
            cp_async16(sau + (r * LDA + ch * 8) * 2,
                       A + (size_t)(row0 + r) * K + kt * 32 + ch * 8);
        }
        #pragma unroll
        for (int i = 0; i < 2; i++) {
            int idx = tid + i * 256;
            int r = idx >> 4, ch = idx & 15;
            cp_async16(sbu + (r * LDB + ch * 8) * 2,
                       Bp + (size_t)(kt * 32 + r) * N + col0 + ch * 8);
        }
        CP_COMMIT();
    };

    float acc[4][8][4];
    #pragma unroll
    for (int i = 0; i < 4; i++)
        #pragma unroll
        for (int j = 0; j < 8; j++)
            #pragma unroll
            for (int e = 0; e < 4; e++) acc[i][j][e] = 0.f;

    issue(0, 0);
    issue(1, 1);

    const uint32_t aLane = (((wm * 64 + (lane & 15)) * LDA) + 8 * (lane >> 4)) * 2;
    const uint32_t bLane = ((((lane & 7) + 8 * ((lane >> 3) & 1)) * LDB)
                            + wn * 64 + 8 * (lane >> 4)) * 2;

    for (int kt = 0; kt < nk; kt++) {
        const int st = kt % 3;
        if (kt + 1 < nk) { CP_WAIT(1); } else { CP_WAIT(0); }
        __syncthreads();
        if (kt + 2 < nk) issue(kt + 2, (kt + 2) % 3);

        const uint32_t aAddr = sb + st * STG_H * 2 + aLane;
        const uint32_t bAddr = sb + st * STG_H * 2 + STG_A * 2 + bLane;
        #pragma unroll
        for (int ks = 0; ks < 2; ks++) {
            uint32_t a[4][4];
            #pragma unroll
            for (int mi = 0; mi < 4; mi++)
                ldsm4(a[mi], aAddr + ks * 32 + mi * 16 * LDA * 2);
            #pragma unroll
            for (int jj = 0; jj < 4; jj++) {
                uint32_t b[4];
                ldsm4t(b, bAddr + ks * 16 * LDB * 2 + jj * 32);
                #pragma unroll
                for (int mi = 0; mi < 4; mi++) {
                    mma16816(acc[mi][2 * jj],     a[mi], b[0], b[1]);
                    mma16816(acc[mi][2 * jj + 1], a[mi], b[2], b[3]);
                }
            }
        }
    }

    const float cs = (SCALEQ && row0 < 512) ? 0.125f * 1.44269504f : 1.f;
    #pragma unroll
    for (int mi = 0; mi < 4; mi++) {
        int r = row0 + wm * 64 + mi * 16 + g;
        #pragma unroll
        for (int j = 0; j < 8; j++) {
            int c = col0 + wn * 64 + 8 * j + 2 * t;
            if constexpr (sizeof(TC) == 2) {
                *(uint32_t*)&Cp[(size_t)r * N + c] =
                    pk(acc[mi][j][0] * cs, acc[mi][j][1] * cs);
                *(uint32_t*)&Cp[(size_t)(r + 8) * N + c] =
                    pk(acc[mi][j][2] * cs, acc[mi][j][3] * cs);
            } else {
                *(float2*)&Cp[(size_t)r * N + c] =
                    make_float2(acc[mi][j][0] * cs, acc[mi][j][1] * cs);
                *(float2*)&Cp[(size_t)(r + 8) * N + c] =
                    make_float2(acc[mi][j][2] * cs, acc[mi][j][3] * cs);
            }
        }
    }

    // ---- GroupNorm partial sums (proj only): warp slice = one 64-row group ----
    if constexpr (GNP) {
        float sum = 0.f, ss = 0.f;
        #pragma unroll
        for (int mi = 0; mi < 4; mi++)
            #pragma unroll
            for (int j = 0; j < 8; j++)
                #pragma unroll
                for (int e = 0; e < 4; e++) {
                    float v = acc[mi][j][e];
                    sum += v;
                    ss  += v * v;
                }
        #pragma unroll
        for (int off = 16; off; off >>= 1) {
            sum += __shfl_xor_sync(0xffffffffu, sum, off);
            ss  += __shfl_xor_sync(0xffffffffu, ss, off);
        }
        __syncthreads();
        float* red = (float*)sh;
        if (lane == 0) { red[warp * 2] = sum; red[warp * 2 + 1] = ss; }
        __syncthreads();
        if (tid < 4) {
            float s = red[(tid * 2) * 2]     + red[(tid * 2 + 1) * 2];
            float q = red[(tid * 2) * 2 + 1] + red[(tid * 2 + 1) * 2 + 1];
            int grp = (row0 >> 6) + tid;
            g_gnp[((bz * 8 + grp) * 8 + blockIdx.x) * 2]     = s;
            g_gnp[((bz * 8 + grp) * 8 + blockIdx.x) * 2 + 1] = q;
        }
    }
}

// ---------------------------------------------------------------------------
// Fused flash attention: 128 rows, 4 warps, exp2f softmax, ONE barrier/tile,
// row-sum via ones-mma (L from the exact fp16 P used in PV).
// ---------------------------------------------------------------------------
#define LDQ 136
#define LDK 72
#define LDO 72
#define ATT_SMEM ((64 * LDQ + 4 * 64 * LDK) * 2)
#define ONES2 0x3C003C00u

__global__ __launch_bounds__(128) void attn_h(
    const __half* __restrict__ qkv, __half* __restrict__ outh)
{
    extern __shared__ __half smh[];
    __half* qs = smh;
    __half* kv = smh + 64 * LDQ;

    const int b = blockIdx.z, h = blockIdx.y;
    const int n0 = blockIdx.x * 128;
    const int tid = threadIdx.x, warp = tid >> 5, lane = tid & 31;
    const int g = lane >> 2, t = lane & 3;
    const int rowbase = warp * 32;

    const __half* q = qkv + (((size_t)b * 3 + 0) * NH + h) * HD * NN;
    const __half* k = qkv + (((size_t)b * 3 + 1) * NH + h) * HD * NN;
    const __half* v = qkv + (((size_t)b * 3 + 2) * NH + h) * HD * NN;

    const uint32_t qb  = smem_u32(qs);
    const uint32_t kvb = smem_u32(kv);
    const uint32_t qLane = ((((lane & 7) + 8 * (lane >> 4)) * LDQ)
                            + rowbase + 8 * ((lane >> 3) & 1)) * 2;
    const uint32_t kLane = ((((lane & 7) + 8 * ((lane >> 3) & 1)) * LDK)
                            + 8 * (lane >> 4)) * 2;
    const uint32_t vLane = ((((lane & 7) + 8 * (lane >> 4)) * LDK)
                            + 8 * ((lane >> 3) & 1)) * 2;

    auto issueKV = [&](int mt, int st) {
        const int m0 = mt * 64;
        const uint32_t kd = kvb + st * (2 * 64 * LDK) * 2;
        const uint32_t vd = kd + (64 * LDK) * 2;
        #pragma unroll
        for (int i = 0; i < 4; i++) {
            int idx = tid + i * 128;
            int d = idx >> 3, ch = idx & 7;
            cp_async16(kd + (d * LDK + ch * 8) * 2, k + (size_t)d * NN + m0 + ch * 8);
            cp_async16(vd + (d * LDK + ch * 8) * 2, v + (size_t)d * NN + m0 + ch * 8);
        }
    };

    // prologue: Q + KV tile 0 in one group
    #pragma unroll
    for (int i = 0; i < 8; i++) {
        int idx = tid + i * 128;
        int d = idx >> 4, ch = idx & 15;
        cp_async16(qb + (d * LDQ + ch * 8) * 2, q + (size_t)d * NN + n0 + ch * 8);
    }
    issueKV(0, 0);
    CP_COMMIT();

    float o[2][8][4];
    float Mx[2][2], L[2][2];
    #pragma unroll
    for (int i = 0; i < 2; i++) {
        #pragma unroll
        for (int j = 0; j < 8; j++)
            #pragma unroll
            for (int e = 0; e < 4; e++) o[i][j][e] = 0.f;
        Mx[i][0] = Mx[i][1] = -1e30f;
        L[i][0] = L[i][1] = 0.f;
    }

    for (int mt = 0; mt < NN / 64; mt++) {
        const int st = mt & 1;
        CP_WAIT(0);
        __syncthreads();   // single barrier: data visible AND prev-tile reads done
        if (mt + 1 < NN / 64) {
            issueKV(mt + 1, st ^ 1);   // safe: stage st^1 last read in iter mt-1
            CP_COMMIT();
        }

        const uint32_t kAddr = kvb + st * (2 * 64 * LDK) * 2 + kLane;
        const uint32_t vAddr = kvb + st * (2 * 64 * LDK) * 2 + (64 * LDK) * 2 + vLane;

        // ---- S = Q * K^T ----
        float s[2][8][4];
        #pragma unroll
        for (int i = 0; i < 2; i++)
            #pragma unroll
            for (int j = 0; j < 8; j++)
                #pragma unroll
                for (int e = 0; e < 4; e++) s[i][j][e] = 0.f;

        #pragma unroll
        for (int ks16 = 0; ks16 < 4; ks16++) {
            uint32_t a[2][4];
            ldsm4t(a[0], qb + qLane + ks16 * 16 * LDQ * 2);
            ldsm4t(a[1], qb + qLane + ks16 * 16 * LDQ * 2 + 32);
            #pragma unroll
            for (int jj = 0; jj < 4; jj++) {
                uint32_t bf[4];
                ldsm4t(bf, kAddr + ks16 * 16 * LDK * 2 + jj * 32);
                mma16816(s[0][2 * jj],     a[0], bf[0], bf[1]);
                mma16816(s[0][2 * jj + 1], a[0], bf[2], bf[3]);
                mma16816(s[1][2 * jj],     a[1], bf[0], bf[1]);
                mma16816(s[1][2 * jj + 1], a[1], bf[2], bf[3]);
            }
        }

        // ---- online softmax (max + exp only; sums via ones-mma below) ----
        #pragma unroll
        for (int i = 0; i < 2; i++) {
            #pragma unroll
            for (int rh = 0; rh < 2; rh++) {
                float tm = -1e30f;
                #pragma unroll
                for (int j = 0; j < 8; j++)
                    tm = fmaxf(tm, fmaxf(s[i][j][2 * rh], s[i][j][2 * rh + 1]));
                tm = fmaxf(tm, __shfl_xor_sync(0xffffffffu, tm, 1));
                tm = fmaxf(tm, __shfl_xor_sync(0xffffffffu, tm, 2));
                float nM = fmaxf(Mx[i][rh], tm);
                float corr = exp2f(Mx[i][rh] - nM);
                Mx[i][rh] = nM;
                #pragma unroll
                for (int j = 0; j < 8; j++) {
                    s[i][j][2 * rh]     = exp2f(s[i][j][2 * rh] - nM);
                    s[i][j][2 * rh + 1] = exp2f(s[i][j][2 * rh + 1] - nM);
                }
                L[i][rh] *= corr;
                #pragma unroll
                for (int j = 0; j < 8; j++) {
                    o[i][j][2 * rh]     *= corr;
                    o[i][j][2 * rh + 1] *= corr;
                }
            }
        }

        // ---- O += P * V^T ; L += P * 1 (ones-mma) ----
        float lsa[2][4];
        #pragma unroll
        for (int i = 0; i < 2; i++)
            #pragma unroll
            for (int e = 0; e < 4; e++) lsa[i][e] = 0.f;

        #pragma unroll
        for (int ms2 = 0; ms2 < 4; ms2++) {
            uint32_t aP[2][4];
            #pragma unroll
            for (int i = 0; i < 2; i++) {
                aP[i][0] = pk(s[i][2 * ms2][0],     s[i][2 * ms2][1]);
                aP[i][1] = pk(s[i][2 * ms2][2],     s[i][2 * ms2][3]);
                aP[i][2] = pk(s[i][2 * ms2 + 1][0], s[i][2 * ms2 + 1][1]);
                aP[i][3] = pk(s[i][2 * ms2 + 1][2], s[i][2 * ms2 + 1][3]);
            }
            #pragma unroll
            for (int jj = 0; jj < 4; jj++) {
                uint32_t bf[4];
                ldsm4(bf, vAddr + jj * 16 * LDK * 2 + ms2 * 32);
                mma16816(o[0][2 * jj],     aP[0], bf[0], bf[1]);
                mma16816(o[0][2 * jj + 1], aP[0], bf[2], bf[3]);
                mma16816(o[1][2 * jj],     aP[1], bf[0], bf[1]);
                mma16816(o[1][2 * jj + 1], aP[1], bf[2], bf[3]);
            }
            mma16816(lsa[0], aP[0], ONES2, ONES2);
            mma16816(lsa[1], aP[1], ONES2, ONES2);
        }
        #pragma unroll
        for (int i = 0; i < 2; i++) {
            L[i][0] += lsa[i][0];
            L[i][1] += lsa[i][2];
        }
    }

    // ---- epilogue: smem transpose -> coalesced fp16 stores ----
    __syncthreads();   // all warps done reading qs before overwrite
    __half* os = smh;
    #pragma unroll
    for (int i = 0; i < 2; i++) {
        float inv0 = 1.f / L[i][0];
        float inv1 = 1.f / L[i][1];
        int rl = rowbase + 16 * i + g;
        #pragma unroll
        for (int j = 0; j < 8; j++) {
            int d = 8 * j + 2 * t;
            *(uint32_t*)&os[rl * LDO + d]       = pk(o[i][j][0] * inv0, o[i][j][1] * inv0);
            *(uint32_t*)&os[(rl + 8) * LDO + d] = pk(o[i][j][2] * inv1, o[i][j][3] * inv1);
        }
    }
    __syncthreads();
    {
        const int d = tid >> 1, seg = (tid & 1) * 64;
        __half* dst = outh + ((size_t)b * CH + h * HD + d) * NN + n0 + seg;
        #pragma unroll
        for (int c8 = 0; c8 < 8; c8++) {
            __half tmp[8];
            #pragma unroll
            for (int r = 0; r < 8; r++)
                tmp[r] = os[(seg + c8 * 8 + r) * LDO + d];
            *(uint4*)&dst[c8 * 8] = *(uint4*)tmp;
        }
    }
}

// ---------------------------------------------------------------------------
// GroupNorm apply (stats from GEMM-epilogue partials) + residual
// ---------------------------------------------------------------------------
__global__ __launch_bounds__(256) void gn_apply(
    const __half* __restrict__ p, const float* __restrict__ x,
    const float* __restrict__ gamma, const float* __restrict__ beta,
    float* __restrict__ out)
{
    const int bg = blockIdx.x >> 3, sp = blockIdx.x & 7;
    float sum = 0.f, ss = 0.f;
    #pragma unroll
    for (int xk = 0; xk < 8; xk++) {
        sum += g_gnp[(bg * 8 + xk) * 2];
        ss  += g_gnp[(bg * 8 + xk) * 2 + 1];
    }
    const float invn = 1.f / 65536.f;
    const float mean = sum * invn;
    const float inv  = rsqrtf(ss * invn - mean * mean + GN_EPS);
    const int grp = bg & 7;

    const size_t base = (size_t)bg * CPG * NN;
    const uint4*  p8 = (const uint4*)(p + base) + sp * 1024;
    const float4* x4 = (const float4*)(x + base) + sp * 2048;
    float4*       o4 = (float4*)(out + base) + sp * 2048;

    #pragma unroll
    for (int it = 0; it < 4; it++) {
        int idx = threadIdx.x + it * 256;
        int c = grp * CPG + sp * 8 + (idx >> 7);
        float ga = gamma[c] * inv, be = beta[c];
        uint4 u = p8[idx];
        const __half2* hp = (const __half2*)&u;
        float4 xa = x4[2 * idx], xb = x4[2 * idx + 1];
        float2 f0 = __half22float2(hp[0]), f1 = __half22float2(hp[1]);
        float2 f2 = __half22float2(hp[2]), f3 = __half22float2(hp[3]);
        float4 ra, rb;
        ra.x = (f0.x - mean) * ga + be + xa.x;
        ra.y = (f0.y - mean) * ga + be + xa.y;
        ra.z = (f1.x - mean) * ga + be + xa.z;
        ra.w = (f1.y - mean) * ga + be + xa.w;
        rb.x = (f2.x - mean) * ga + be + xb.x;
        rb.y = (f2.y - mean) * ga + be + xb.y;
        rb.z = (f3.x - mean) * ga + be + xb.z;
        rb.w = (f3.y - mean) * ga + be + xb.w;
        o4[2 * idx]     = ra;
        o4[2 * idx + 1] = rb;
    }
}

// ---------------------------------------------------------------------------
extern "C" void kernel_launch(void* const* d_in, const int* in_sizes, int n_in,
                              void* d_out, int out_size)
{
    const float* x      = (const float*)d_in[0];
    const float* w_qkv  = (const float*)d_in[1];
    const float* w_proj = (const float*)d_in[2];
    const float* gamma  = (const float*)d_in[3];
    const float* beta   = (const float*)d_in[4];
    float* out = (float*)d_out;

    __half *w16, *wp16, *x16, *qkvh, *atth, *projh;
    cudaGetSymbolAddress((void**)&w16,   g_w16);
    cudaGetSymbolAddress((void**)&wp16,  g_wp16);
    cudaGetSymbolAddress((void**)&x16,   g_x16);
    cudaGetSymbolAddress((void**)&qkvh,  g_qkvh);
    cudaGetSymbolAddress((void**)&atth,  g_atth);
    cudaGetSymbolAddress((void**)&projh, g_projh);

    static bool attr_set = false;
    if (!attr_set) {
        cudaFuncSetAttribute(attn_h,
            cudaFuncAttributeMaxDynamicSharedMemorySize, ATT_SMEM);
        cudaFuncSetAttribute((const void*)gemm_a<__half, true, false>,
            cudaFuncAttributeMaxDynamicSharedMemorySize, GSMEM);
        cudaFuncSetAttribute((const void*)gemm_a<__half, false, true>,
            cudaFuncAttributeMaxDynamicSharedMemorySize, GSMEM);
        attr_set = true;
    }

    // 0) single-launch fp32 -> fp16 conversion
    cvt_all<<<1280, 256>>>(w_qkv, w16, w_proj, wp16, x, x16);

    // 1) QKV projection (Q rows scaled by 0.125*log2e), 256x128 tiles
    gemm_a<__half, true, false><<<dim3(NN / 128, (3 * CH) / 256, BATCH), 256, GSMEM>>>(
        w16, x16, qkvh, 3 * CH, NN, CH);

    // 2) Fused flash attention (1 barrier/tile, ones-mma row sums)
    attn_h<<<dim3(NN / 128, NH, BATCH), 128, ATT_SMEM>>>(qkvh, atth);

    // 3) Output projection -> fp16, GN partials fused into epilogue
    gemm_a<__half, false, true><<<dim3(NN / 128, CH / 256, BATCH), 256, GSMEM>>>(
        wp16, atth, projh, CH, NN, CH);

    // 4) GroupNorm apply + residual (stats from fused partials)
    gn_apply<<<512, 256>>>(projh, x, gamma, beta, out);
}

// round 15
// speedup vs baseline: 1.1374x; 1.0822x over previous
#include <cuda_runtime.h>
#include <cuda_fp16.h>
#include <math.h>
#include <stdint.h>

#define BATCH 8
#define CH    512
#define NN    1024
#define NH    8
#define HD    64
#define CPG   64
#define GN_EPS 1e-5f

// fp16 scratch
__device__ __half g_w16[(size_t)3 * CH * CH];
__device__ __half g_wp16[(size_t)CH * CH];
__device__ __half g_x16[(size_t)BATCH * CH * NN];
__device__ __half g_qkvh[(size_t)BATCH * 3 * CH * NN];
__device__ __half g_atth[(size_t)BATCH * CH * NN];
__device__ __half g_projh[(size_t)BATCH * CH * NN];
__device__ float  g_gnp[BATCH * 8 * 8 * 2];   // [b*8+grp][xblk][{sum,ss}]

// ---------------------------------------------------------------------------
// helpers
// ---------------------------------------------------------------------------
__device__ __forceinline__ uint32_t smem_u32(const void* p) {
    uint32_t a;
    asm("{ .reg .u64 t; cvta.to.shared.u64 t, %1; cvt.u32.u64 %0, t; }" : "=r"(a) : "l"(p));
    return a;
}
__device__ __forceinline__ uint32_t pk(float x, float y) {
    __half2 h = __floats2half2_rn(x, y);
    return *(uint32_t*)&h;
}
__device__ __forceinline__ void mma16816(float* c, const uint32_t* a,
                                         uint32_t b0, uint32_t b1) {
    asm volatile(
        "mma.sync.aligned.m16n8k16.row.col.f32.f16.f16.f32 "
        "{%0,%1,%2,%3},{%4,%5,%6,%7},{%8,%9},{%0,%1,%2,%3};"
        : "+f"(c[0]), "+f"(c[1]), "+f"(c[2]), "+f"(c[3])
        : "r"(a[0]), "r"(a[1]), "r"(a[2]), "r"(a[3]), "r"(b0), "r"(b1));
}
__device__ __forceinline__ void ldsm4(uint32_t* r, uint32_t addr) {
    asm volatile("ldmatrix.sync.aligned.m8n8.x4.shared.b16 {%0,%1,%2,%3}, [%4];"
        : "=r"(r[0]), "=r"(r[1]), "=r"(r[2]), "=r"(r[3]) : "r"(addr));
}
__device__ __forceinline__ void ldsm4t(uint32_t* r, uint32_t addr) {
    asm volatile("ldmatrix.sync.aligned.m8n8.x4.trans.shared.b16 {%0,%1,%2,%3}, [%4];"
        : "=r"(r[0]), "=r"(r[1]), "=r"(r[2]), "=r"(r[3]) : "r"(addr));
}
__device__ __forceinline__ void cp_async16(uint32_t dst, const void* src) {
    asm volatile("cp.async.ca.shared.global [%0], [%1], 16;" :: "r"(dst), "l"(src));
}
#define CP_COMMIT() asm volatile("cp.async.commit_group;" ::: "memory")
#define CP_WAIT(n)  asm volatile("cp.async.wait_group %0;" :: "n"(n) : "memory")

// ---------------------------------------------------------------------------
// single-launch fp32 -> fp16 conversion
// ---------------------------------------------------------------------------
#define CVT_N1 ((3 * CH * CH) / 4)
#define CVT_N2 ((CH * CH) / 4)
#define CVT_N3 ((BATCH * CH * NN) / 4)
__global__ __launch_bounds__(256) void cvt_all(
    const float* __restrict__ w, __half* __restrict__ w16,
    const float* __restrict__ wp, __half* __restrict__ wp16,
    const float* __restrict__ x, __half* __restrict__ x16)
{
    const int total = CVT_N1 + CVT_N2 + CVT_N3;
    for (int i = blockIdx.x * 256 + threadIdx.x; i < total; i += gridDim.x * 256) {
        const float* s; __half* d; int j;
        if (i < CVT_N1)                { s = w;  d = w16;  j = i; }
        else if (i < CVT_N1 + CVT_N2)  { s = wp; d = wp16; j = i - CVT_N1; }
        else                           { s = x;  d = x16;  j = i - CVT_N1 - CVT_N2; }
        float4 v = *(const float4*)&s[(size_t)j * 4];
        *(uint2*)&d[(size_t)j * 4] = make_uint2(pk(v.x, v.y), pk(v.z, v.w));
    }
}

// ---------------------------------------------------------------------------
// all-fp16 cp.async 2-stage k64 GEMM, single barrier per k-tile.
// CTA 256x128, 8 warps (4x2), warp tile 64x64.
// GNP: emit GroupNorm partial sums (proj).
// ---------------------------------------------------------------------------
#define LDA 72                    // 64 k halves + 8 pad
#define LDB 136
#define STG_A (256 * LDA)         // 18432 halves
#define STG_B (64 * LDB)          // 8704 halves
#define STG_H (STG_A + STG_B)
#define GSMEM (2 * STG_H * 2)     // 108544 bytes

template<typename TC, bool SCALEQ, bool GNP>
__global__ __launch_bounds__(256) void gemm_a(
    const __half* __restrict__ A, const __half* __restrict__ Bg,
    TC* __restrict__ Cg, int M, int N, int K)
{
    extern __shared__ __half sh[];

    const int bz = blockIdx.z;
    const __half* Bp = Bg + (size_t)bz * K * N;
    TC*           Cp = Cg + (size_t)bz * M * N;

    const int tid = threadIdx.x;
    const int warp = tid >> 5, lane = tid & 31;
    const int wm = warp >> 1, wn = warp & 1;
    const int g = lane >> 2, t = lane & 3;
    const int row0 = blockIdx.y * 256;
    const int col0 = blockIdx.x * 128;
    const uint32_t sb = smem_u32(sh);
    const int nk = K / 64;

    auto issue = [&](int kt, int st) {
        const uint32_t sau = sb + st * STG_H * 2;
        const uint32_t sbu = sau + STG_A * 2;
        // A: 256 rows x 64 k = 2048 chunks, 8/thread
        #pragma unroll
        for (int i = 0; i < 8; i++) {
            int idx = tid + i * 256;
            int r = idx >> 3, ch = idx & 7;
            cp_async16(sau + (r * LDA + ch * 8) * 2,
                       A + (size_t)(row0 + r) * K + kt * 64 + ch * 8);
        }
        // B: 64 rows x 128 n = 1024 chunks, 4/thread
        #pragma unroll
        for (int i = 0; i < 4; i++) {
            int idx = tid + i * 256;
            int r = idx >> 4, ch = idx & 15;
            cp_async16(sbu + (r * LDB + ch * 8) * 2,
                       Bp + (size_t)(kt * 64 + r) * N + col0 + ch * 8);
        }
        CP_COMMIT();
    };

    float acc[4][8][4];
    #pragma unroll
    for (int i = 0; i < 4; i++)
        #pragma unroll
        for (int j = 0; j < 8; j++)
            #pragma unroll
            for (int e = 0; e < 4; e++) acc[i][j][e] = 0.f;

    issue(0, 0);

    const uint32_t aLane = (((wm * 64 + (lane & 15)) * LDA) + 8 * (lane >> 4)) * 2;
    const uint32_t bLane = ((((lane & 7) + 8 * ((lane >> 3) & 1)) * LDB)
                            + wn * 64 + 8 * (lane >> 4)) * 2;

    for (int kt = 0; kt < nk; kt++) {
        const int st = kt & 1;
        CP_WAIT(0);
        __syncthreads();   // single barrier: data ready AND prev-tile reads done
        if (kt + 1 < nk) issue(kt + 1, st ^ 1);

        const uint32_t aAddr = sb + st * STG_H * 2 + aLane;
        const uint32_t bAddr = sb + st * STG_H * 2 + STG_A * 2 + bLane;
        #pragma unroll
        for (int ks = 0; ks < 4; ks++) {
            uint32_t a[4][4];
            #pragma unroll
            for (int mi = 0; mi < 4; mi++)
                ldsm4(a[mi], aAddr + ks * 32 + mi * 16 * LDA * 2);
            #pragma unroll
            for (int jj = 0; jj < 4; jj++) {
                uint32_t b[4];
                ldsm4t(b, bAddr + ks * 16 * LDB * 2 + jj * 32);
                #pragma unroll
                for (int mi = 0; mi < 4; mi++) {
                    mma16816(acc[mi][2 * jj],     a[mi], b[0], b[1]);
                    mma16816(acc[mi][2 * jj + 1], a[mi], b[2], b[3]);
                }
            }
        }
    }

    const float cs = (SCALEQ && row0 < 512) ? 0.125f * 1.44269504f : 1.f;
    #pragma unroll
    for (int mi = 0; mi < 4; mi++) {
        int r = row0 + wm * 64 + mi * 16 + g;
        #pragma unroll
        for (int j = 0; j < 8; j++) {
            int c = col0 + wn * 64 + 8 * j + 2 * t;
            if constexpr (sizeof(TC) == 2) {
                *(uint32_t*)&Cp[(size_t)r * N + c] =
                    pk(acc[mi][j][0] * cs, acc[mi][j][1] * cs);
                *(uint32_t*)&Cp[(size_t)(r + 8) * N + c] =
                    pk(acc[mi][j][2] * cs, acc[mi][j][3] * cs);
            } else {
                *(float2*)&Cp[(size_t)r * N + c] =
                    make_float2(acc[mi][j][0] * cs, acc[mi][j][1] * cs);
                *(float2*)&Cp[(size_t)(r + 8) * N + c] =
                    make_float2(acc[mi][j][2] * cs, acc[mi][j][3] * cs);
            }
        }
    }

    // ---- GroupNorm partial sums (proj only): warp slice = one 64-row group ----
    if constexpr (GNP) {
        float sum = 0.f, ss = 0.f;
        #pragma unroll
        for (int mi = 0; mi < 4; mi++)
            #pragma unroll
            for (int j = 0; j < 8; j++)
                #pragma unroll
                for (int e = 0; e < 4; e++) {
                    float v = acc[mi][j][e];
                    sum += v;
                    ss  += v * v;
                }
        #pragma unroll
        for (int off = 16; off; off >>= 1) {
            sum += __shfl_xor_sync(0xffffffffu, sum, off);
            ss  += __shfl_xor_sync(0xffffffffu, ss, off);
        }
        __syncthreads();
        float* red = (float*)sh;
        if (lane == 0) { red[warp * 2] = sum; red[warp * 2 + 1] = ss; }
        __syncthreads();
        if (tid < 4) {
            float s = red[(tid * 2) * 2]     + red[(tid * 2 + 1) * 2];
            float q = red[(tid * 2) * 2 + 1] + red[(tid * 2 + 1) * 2 + 1];
            int grp = (row0 >> 6) + tid;
            g_gnp[((bz * 8 + grp) * 8 + blockIdx.x) * 2]     = s;
            g_gnp[((bz * 8 + grp) * 8 + blockIdx.x) * 2 + 1] = q;
        }
    }
}

// ---------------------------------------------------------------------------
// Fused flash attention (R12 best: 128 rows, 1 barrier/tile, ones-mma sums)
// ---------------------------------------------------------------------------
#define LDQ 136
#define LDK 72
#define LDO 72
#define ATT_SMEM ((64 * LDQ + 4 * 64 * LDK) * 2)
#define ONES2 0x3C003C00u

__global__ __launch_bounds__(128) void attn_h(
    const __half* __restrict__ qkv, __half* __restrict__ outh)
{
    extern __shared__ __half smh[];
    __half* qs = smh;
    __half* kv = smh + 64 * LDQ;

    const int b = blockIdx.z, h = blockIdx.y;
    const int n0 = blockIdx.x * 128;
    const int tid = threadIdx.x, warp = tid >> 5, lane = tid & 31;
    const int g = lane >> 2, t = lane & 3;
    const int rowbase = warp * 32;

    const __half* q = qkv + (((size_t)b * 3 + 0) * NH + h) * HD * NN;
    const __half* k = qkv + (((size_t)b * 3 + 1) * NH + h) * HD * NN;
    const __half* v = qkv + (((size_t)b * 3 + 2) * NH + h) * HD * NN;

    const uint32_t qb  = smem_u32(qs);
    const uint32_t kvb = smem_u32(kv);
    const uint32_t qLane = ((((lane & 7) + 8 * (lane >> 4)) * LDQ)
                            + rowbase + 8 * ((lane >> 3) & 1)) * 2;
    const uint32_t kLane = ((((lane & 7) + 8 * ((lane >> 3) & 1)) * LDK)
                            + 8 * (lane >> 4)) * 2;
    const uint32_t vLane = ((((lane & 7) + 8 * (lane >> 4)) * LDK)
                            + 8 * ((lane >> 3) & 1)) * 2;

    auto issueKV = [&](int mt, int st) {
        const int m0 = mt * 64;
        const uint32_t kd = kvb + st * (2 * 64 * LDK) * 2;
        const uint32_t vd = kd + (64 * LDK) * 2;
        #pragma unroll
        for (int i = 0; i < 4; i++) {
            int idx = tid + i * 128;
            int d = idx >> 3, ch = idx & 7;
            cp_async16(kd + (d * LDK + ch * 8) * 2, k + (size_t)d * NN + m0 + ch * 8);
            cp_async16(vd + (d * LDK + ch * 8) * 2, v + (size_t)d * NN + m0 + ch * 8);
        }
    };

    #pragma unroll
    for (int i = 0; i < 8; i++) {
        int idx = tid + i * 128;
        int d = idx >> 4, ch = idx & 15;
        cp_async16(qb + (d * LDQ + ch * 8) * 2, q + (size_t)d * NN + n0 + ch * 8);
    }
    issueKV(0, 0);
    CP_COMMIT();

    float o[2][8][4];
    float Mx[2][2], L[2][2];
    #pragma unroll
    for (int i = 0; i < 2; i++) {
        #pragma unroll
        for (int j = 0; j < 8; j++)
            #pragma unroll
            for (int e = 0; e < 4; e++) o[i][j][e] = 0.f;
        Mx[i][0] = Mx[i][1] = -1e30f;
        L[i][0] = L[i][1] = 0.f;
    }

    for (int mt = 0; mt < NN / 64; mt++) {
        const int st = mt & 1;
        CP_WAIT(0);
        __syncthreads();
        if (mt + 1 < NN / 64) {
            issueKV(mt + 1, st ^ 1);
            CP_COMMIT();
        }

        const uint32_t kAddr = kvb + st * (2 * 64 * LDK) * 2 + kLane;
        const uint32_t vAddr = kvb + st * (2 * 64 * LDK) * 2 + (64 * LDK) * 2 + vLane;

        float s[2][8][4];
        #pragma unroll
        for (int i = 0; i < 2; i++)
            #pragma unroll
            for (int j = 0; j < 8; j++)
                #pragma unroll
                for (int e = 0; e < 4; e++) s[i][j][e] = 0.f;

        #pragma unroll
        for (int ks16 = 0; ks16 < 4; ks16++) {
            uint32_t a[2][4];
            ldsm4t(a[0], qb + qLane + ks16 * 16 * LDQ * 2);
            ldsm4t(a[1], qb + qLane + ks16 * 16 * LDQ * 2 + 32);
            #pragma unroll
            for (int jj = 0; jj < 4; jj++) {
                uint32_t bf[4];
                ldsm4t(bf, kAddr + ks16 * 16 * LDK * 2 + jj * 32);
                mma16816(s[0][2 * jj],     a[0], bf[0], bf[1]);
                mma16816(s[0][2 * jj + 1], a[0], bf[2], bf[3]);
                mma16816(s[1][2 * jj],     a[1], bf[0], bf[1]);
                mma16816(s[1][2 * jj + 1], a[1], bf[2], bf[3]);
            }
        }

        #pragma unroll
        for (int i = 0; i < 2; i++) {
            #pragma unroll
            for (int rh = 0; rh < 2; rh++) {
                float tm = -1e30f;
                #pragma unroll
                for (int j = 0; j < 8; j++)
                    tm = fmaxf(tm, fmaxf(s[i][j][2 * rh], s[i][j][2 * rh + 1]));
                tm = fmaxf(tm, __shfl_xor_sync(0xffffffffu, tm, 1));
                tm = fmaxf(tm, __shfl_xor_sync(0xffffffffu, tm, 2));
                float nM = fmaxf(Mx[i][rh], tm);
                float corr = exp2f(Mx[i][rh] - nM);
                Mx[i][rh] = nM;
                #pragma unroll
                for (int j = 0; j < 8; j++) {
                    s[i][j][2 * rh]     = exp2f(s[i][j][2 * rh] - nM);
                    s[i][j][2 * rh + 1] = exp2f(s[i][j][2 * rh + 1] - nM);
                }
                L[i][rh] *= corr;
                #pragma unroll
                for (int j = 0; j < 8; j++) {
                    o[i][j][2 * rh]     *= corr;
                    o[i][j][2 * rh + 1] *= corr;
                }
            }
        }

        float lsa[2][4];
        #pragma unroll
        for (int i = 0; i < 2; i++)
            #pragma unroll
            for (int e = 0; e < 4; e++) lsa[i][e] = 0.f;

        #pragma unroll
        for (int ms2 = 0; ms2 < 4; ms2++) {
            uint32_t aP[2][4];
            #pragma unroll
            for (int i = 0; i < 2; i++) {
                aP[i][0] = pk(s[i][2 * ms2][0],     s[i][2 * ms2][1]);
                aP[i][1] = pk(s[i][2 * ms2][2],     s[i][2 * ms2][3]);
                aP[i][2] = pk(s[i][2 * ms2 + 1][0], s[i][2 * ms2 + 1][1]);
                aP[i][3] = pk(s[i][2 * ms2 + 1][2], s[i][2 * ms2 + 1][3]);
            }
            #pragma unroll
            for (int jj = 0; jj < 4; jj++) {
                uint32_t bf[4];
                ldsm4(bf, vAddr + jj * 16 * LDK * 2 + ms2 * 32);
                mma16816(o[0][2 * jj],     aP[0], bf[0], bf[1]);
                mma16816(o[0][2 * jj + 1], aP[0], bf[2], bf[3]);
                mma16816(o[1][2 * jj],     aP[1], bf[0], bf[1]);
                mma16816(o[1][2 * jj + 1], aP[1], bf[2], bf[3]);
            }
            mma16816(lsa[0], aP[0], ONES2, ONES2);
            mma16816(lsa[1], aP[1], ONES2, ONES2);
        }
        #pragma unroll
        for (int i = 0; i < 2; i++) {
            L[i][0] += lsa[i][0];
            L[i][1] += lsa[i][2];
        }
    }

    __syncthreads();
    __half* os = smh;
    #pragma unroll
    for (int i = 0; i < 2; i++) {
        float inv0 = 1.f / L[i][0];
        float inv1 = 1.f / L[i][1];
        int rl = rowbase + 16 * i + g;
        #pragma unroll
        for (int j = 0; j < 8; j++) {
            int d = 8 * j + 2 * t;
            *(uint32_t*)&os[rl * LDO + d]       = pk(o[i][j][0] * inv0, o[i][j][1] * inv0);
            *(uint32_t*)&os[(rl + 8) * LDO + d] = pk(o[i][j][2] * inv1, o[i][j][3] * inv1);
        }
    }
    __syncthreads();
    {
        const int d = tid >> 1, seg = (tid & 1) * 64;
        __half* dst = outh + ((size_t)b * CH + h * HD + d) * NN + n0 + seg;
        #pragma unroll
        for (int c8 = 0; c8 < 8; c8++) {
            __half tmp[8];
            #pragma unroll
            for (int r = 0; r < 8; r++)
                tmp[r] = os[(seg + c8 * 8 + r) * LDO + d];
            *(uint4*)&dst[c8 * 8] = *(uint4*)tmp;
        }
    }
}

// ---------------------------------------------------------------------------
// GroupNorm apply (stats from GEMM-epilogue partials) + residual
// ---------------------------------------------------------------------------
__global__ __launch_bounds__(256) void gn_apply(
    const __half* __restrict__ p, const float* __restrict__ x,
    const float* __restrict__ gamma, const float* __restrict__ beta,
    float* __restrict__ out)
{
    const int bg = blockIdx.x >> 3, sp = blockIdx.x & 7;
    float sum = 0.f, ss = 0.f;
    #pragma unroll
    for (int xk = 0; xk < 8; xk++) {
        sum += g_gnp[(bg * 8 + xk) * 2];
        ss  += g_gnp[(bg * 8 + xk) * 2 + 1];
    }
    const float invn = 1.f / 65536.f;
    const float mean = sum * invn;
    const float inv  = rsqrtf(ss * invn - mean * mean + GN_EPS);
    const int grp = bg & 7;

    const size_t base = (size_t)bg * CPG * NN;
    const uint4*  p8 = (const uint4*)(p + base) + sp * 1024;
    const float4* x4 = (const float4*)(x + base) + sp * 2048;
    float4*       o4 = (float4*)(out + base) + sp * 2048;

    #pragma unroll
    for (int it = 0; it < 4; it++) {
        int idx = threadIdx.x + it * 256;
        int c = grp * CPG + sp * 8 + (idx >> 7);
        float ga = gamma[c] * inv, be = beta[c];
        uint4 u = p8[idx];
        const __half2* hp = (const __half2*)&u;
        float4 xa = x4[2 * idx], xb = x4[2 * idx + 1];
        float2 f0 = __half22float2(hp[0]), f1 = __half22float2(hp[1]);
        float2 f2 = __half22float2(hp[2]), f3 = __half22float2(hp[3]);
        float4 ra, rb;
        ra.x = (f0.x - mean) * ga + be + xa.x;
        ra.y = (f0.y - mean) * ga + be + xa.y;
        ra.z = (f1.x - mean) * ga + be + xa.z;
        ra.w = (f1.y - mean) * ga + be + xa.w;
        rb.x = (f2.x - mean) * ga + be + xb.x;
        rb.y = (f2.y - mean) * ga + be + xb.y;
        rb.z = (f3.x - mean) * ga + be + xb.z;
        rb.w = (f3.y - mean) * ga + be + xb.w;
        o4[2 * idx]     = ra;
        o4[2 * idx + 1] = rb;
    }
}

// ---------------------------------------------------------------------------
extern "C" void kernel_launch(void* const* d_in, const int* in_sizes, int n_in,
                              void* d_out, int out_size)
{
    const float* x      = (const float*)d_in[0];
    const float* w_qkv  = (const float*)d_in[1];
    const float* w_proj = (const float*)d_in[2];
    const float* gamma  = (const float*)d_in[3];
    const float* beta   = (const float*)d_in[4];
    float* out = (float*)d_out;

    __half *w16, *wp16, *x16, *qkvh, *atth, *projh;
    cudaGetSymbolAddress((void**)&w16,   g_w16);
    cudaGetSymbolAddress((void**)&wp16,  g_wp16);
    cudaGetSymbolAddress((void**)&x16,   g_x16);
    cudaGetSymbolAddress((void**)&qkvh,  g_qkvh);
    cudaGetSymbolAddress((void**)&atth,  g_atth);
    cudaGetSymbolAddress((void**)&projh, g_projh);

    static bool attr_set = false;
    if (!attr_set) {
        cudaFuncSetAttribute(attn_h,
            cudaFuncAttributeMaxDynamicSharedMemorySize, ATT_SMEM);
        cudaFuncSetAttribute((const void*)gemm_a<__half, true, false>,
            cudaFuncAttributeMaxDynamicSharedMemorySize, GSMEM);
        cudaFuncSetAttribute((const void*)gemm_a<__half, false, true>,
            cudaFuncAttributeMaxDynamicSharedMemorySize, GSMEM);
        attr_set = true;
    }

    // 0) single-launch fp32 -> fp16 conversion
    cvt_all<<<1280, 256>>>(w_qkv, w16, w_proj, wp16, x, x16);

    // 1) QKV projection (Q rows scaled by 0.125*log2e), 256x128 tiles, k64
    gemm_a<__half, true, false><<<dim3(NN / 128, (3 * CH) / 256, BATCH), 256, GSMEM>>>(
        w16, x16, qkvh, 3 * CH, NN, CH);

    // 2) Fused flash attention
    attn_h<<<dim3(NN / 128, NH, BATCH), 128, ATT_SMEM>>>(qkvh, atth);

    // 3) Output projection -> fp16, GN partials fused into epilogue, k64
    gemm_a<__half, false, true><<<dim3(NN / 128, CH / 256, BATCH), 256, GSMEM>>>(
        wp16, atth, projh, CH, NN, CH);

    // 4) GroupNorm apply + residual (stats from fused partials)
    gn_apply<<<512, 256>>>(projh, x, gamma, beta, out);
}

// round 16
// speedup vs baseline: 1.1401x; 1.0024x over previous
#include <cuda_runtime.h>
#include <cuda_fp16.h>
#include <math.h>
#include <stdint.h>

#define BATCH 8
#define CH    512
#define NN    1024
#define NH    8
#define HD    64
#define CPG   64
#define GN_EPS 1e-5f

// fp16 scratch
__device__ __half g_w16[(size_t)3 * CH * CH];
__device__ __half g_wp16[(size_t)CH * CH];
__device__ __half g_x16[(size_t)BATCH * CH * NN];
__device__ __half g_qkvh[(size_t)BATCH * 3 * CH * NN];
__device__ __half g_atth[(size_t)BATCH * CH * NN];
__device__ __half g_projh[(size_t)BATCH * CH * NN];
__device__ float  g_gnp[BATCH * 8 * 8 * 2];   // [b*8+grp][xblk][{sum,ss}]

// ---------------------------------------------------------------------------
// helpers
// ---------------------------------------------------------------------------
__device__ __forceinline__ uint32_t smem_u32(const void* p) {
    uint32_t a;
    asm("{ .reg .u64 t; cvta.to.shared.u64 t, %1; cvt.u32.u64 %0, t; }" : "=r"(a) : "l"(p));
    return a;
}
__device__ __forceinline__ uint32_t pk(float x, float y) {
    __half2 h = __floats2half2_rn(x, y);
    return *(uint32_t*)&h;
}
__device__ __forceinline__ uint32_t h2exp2(uint32_t x) {
    uint32_t r;
    asm("ex2.approx.f16x2 %0, %1;" : "=r"(r) : "r"(x));
    return r;
}
__device__ __forceinline__ void mma16816(float* c, const uint32_t* a,
                                         uint32_t b0, uint32_t b1) {
    asm volatile(
        "mma.sync.aligned.m16n8k16.row.col.f32.f16.f16.f32 "
        "{%0,%1,%2,%3},{%4,%5,%6,%7},{%8,%9},{%0,%1,%2,%3};"
        : "+f"(c[0]), "+f"(c[1]), "+f"(c[2]), "+f"(c[3])
        : "r"(a[0]), "r"(a[1]), "r"(a[2]), "r"(a[3]), "r"(b0), "r"(b1));
}
__device__ __forceinline__ void ldsm4(uint32_t* r, uint32_t addr) {
    asm volatile("ldmatrix.sync.aligned.m8n8.x4.shared.b16 {%0,%1,%2,%3}, [%4];"
        : "=r"(r[0]), "=r"(r[1]), "=r"(r[2]), "=r"(r[3]) : "r"(addr));
}
__device__ __forceinline__ void ldsm4t(uint32_t* r, uint32_t addr) {
    asm volatile("ldmatrix.sync.aligned.m8n8.x4.trans.shared.b16 {%0,%1,%2,%3}, [%4];"
        : "=r"(r[0]), "=r"(r[1]), "=r"(r[2]), "=r"(r[3]) : "r"(addr));
}
__device__ __forceinline__ void cp_async16(uint32_t dst, const void* src) {
    asm volatile("cp.async.ca.shared.global [%0], [%1], 16;" :: "r"(dst), "l"(src));
}
#define CP_COMMIT() asm volatile("cp.async.commit_group;" ::: "memory")
#define CP_WAIT(n)  asm volatile("cp.async.wait_group %0;" :: "n"(n) : "memory")

// ---------------------------------------------------------------------------
// single-launch fp32 -> fp16 conversion
// ---------------------------------------------------------------------------
#define CVT_N1 ((3 * CH * CH) / 4)
#define CVT_N2 ((CH * CH) / 4)
#define CVT_N3 ((BATCH * CH * NN) / 4)
__global__ __launch_bounds__(256) void cvt_all(
    const float* __restrict__ w, __half* __restrict__ w16,
    const float* __restrict__ wp, __half* __restrict__ wp16,
    const float* __restrict__ x, __half* __restrict__ x16)
{
    const int total = CVT_N1 + CVT_N2 + CVT_N3;
    for (int i = blockIdx.x * 256 + threadIdx.x; i < total; i += gridDim.x * 256) {
        const float* s; __half* d; int j;
        if (i < CVT_N1)                { s = w;  d = w16;  j = i; }
        else if (i < CVT_N1 + CVT_N2)  { s = wp; d = wp16; j = i - CVT_N1; }
        else                           { s = x;  d = x16;  j = i - CVT_N1 - CVT_N2; }
        float4 v = *(const float4*)&s[(size_t)j * 4];
        *(uint2*)&d[(size_t)j * 4] = make_uint2(pk(v.x, v.y), pk(v.z, v.w));
    }
}

// ---------------------------------------------------------------------------
// all-fp16 cp.async 2-stage k64 GEMM, single barrier per k-tile.
// CTA 256x128, 8 warps (4x2), warp tile 64x64.
// GNP: emit GroupNorm partial sums (proj).
// ---------------------------------------------------------------------------
#define LDA 72                    // 64 k halves + 8 pad
#define LDB 136
#define STG_A (256 * LDA)
#define STG_B (64 * LDB)
#define STG_H (STG_A + STG_B)
#define GSMEM (2 * STG_H * 2)

template<typename TC, bool SCALEQ, bool GNP>
__global__ __launch_bounds__(256) void gemm_a(
    const __half* __restrict__ A, const __half* __restrict__ Bg,
    TC* __restrict__ Cg, int M, int N, int K)
{
    extern __shared__ __half sh[];

    const int bz = blockIdx.z;
    const __half* Bp = Bg + (size_t)bz * K * N;
    TC*           Cp = Cg + (size_t)bz * M * N;

    const int tid = threadIdx.x;
    const int warp = tid >> 5, lane = tid & 31;
    const int wm = warp >> 1, wn = warp & 1;
    const int g = lane >> 2, t = lane & 3;
    const int row0 = blockIdx.y * 256;
    const int col0 = blockIdx.x * 128;
    const uint32_t sb = smem_u32(sh);
    const int nk = K / 64;

    auto issue = [&](int kt, int st) {
        const uint32_t sau = sb + st * STG_H * 2;
        const uint32_t sbu = sau + STG_A * 2;
        #pragma unroll
        for (int i = 0; i < 8; i++) {
            int idx = tid + i * 256;
            int r = idx >> 3, ch = idx & 7;
            cp_async16(sau + (r * LDA + ch * 8) * 2,
                       A + (size_t)(row0 + r) * K + kt * 64 + ch * 8);
        }
        #pragma unroll
        for (int i = 0; i < 4; i++) {
            int idx = tid + i * 256;
            int r = idx >> 4, ch = idx & 15;
            cp_async16(sbu + (r * LDB + ch * 8) * 2,
                       Bp + (size_t)(kt * 64 + r) * N + col0 + ch * 8);
        }
        CP_COMMIT();
    };

    float acc[4][8][4];
    #pragma unroll
    for (int i = 0; i < 4; i++)
        #pragma unroll
        for (int j = 0; j < 8; j++)
            #pragma unroll
            for (int e = 0; e < 4; e++) acc[i][j][e] = 0.f;

    issue(0, 0);

    const uint32_t aLane = (((wm * 64 + (lane & 15)) * LDA) + 8 * (lane >> 4)) * 2;
    const uint32_t bLane = ((((lane & 7) + 8 * ((lane >> 3) & 1)) * LDB)
                            + wn * 64 + 8 * (lane >> 4)) * 2;

    for (int kt = 0; kt < nk; kt++) {
        const int st = kt & 1;
        CP_WAIT(0);
        __syncthreads();
        if (kt + 1 < nk) issue(kt + 1, st ^ 1);

        const uint32_t aAddr = sb + st * STG_H * 2 + aLane;
        const uint32_t bAddr = sb + st * STG_H * 2 + STG_A * 2 + bLane;
        #pragma unroll
        for (int ks = 0; ks < 4; ks++) {
            uint32_t a[4][4];
            #pragma unroll
            for (int mi = 0; mi < 4; mi++)
                ldsm4(a[mi], aAddr + ks * 32 + mi * 16 * LDA * 2);
            #pragma unroll
            for (int jj = 0; jj < 4; jj++) {
                uint32_t b[4];
                ldsm4t(b, bAddr + ks * 16 * LDB * 2 + jj * 32);
                #pragma unroll
                for (int mi = 0; mi < 4; mi++) {
                    mma16816(acc[mi][2 * jj],     a[mi], b[0], b[1]);
                    mma16816(acc[mi][2 * jj + 1], a[mi], b[2], b[3]);
                }
            }
        }
    }

    const float cs = (SCALEQ && row0 < 512) ? 0.125f * 1.44269504f : 1.f;
    #pragma unroll
    for (int mi = 0; mi < 4; mi++) {
        int r = row0 + wm * 64 + mi * 16 + g;
        #pragma unroll
        for (int j = 0; j < 8; j++) {
            int c = col0 + wn * 64 + 8 * j + 2 * t;
            if constexpr (sizeof(TC) == 2) {
                *(uint32_t*)&Cp[(size_t)r * N + c] =
                    pk(acc[mi][j][0] * cs, acc[mi][j][1] * cs);
                *(uint32_t*)&Cp[(size_t)(r + 8) * N + c] =
                    pk(acc[mi][j][2] * cs, acc[mi][j][3] * cs);
            } else {
                *(float2*)&Cp[(size_t)r * N + c] =
                    make_float2(acc[mi][j][0] * cs, acc[mi][j][1] * cs);
                *(float2*)&Cp[(size_t)(r + 8) * N + c] =
                    make_float2(acc[mi][j][2] * cs, acc[mi][j][3] * cs);
            }
        }
    }

    if constexpr (GNP) {
        float sum = 0.f, ss = 0.f;
        #pragma unroll
        for (int mi = 0; mi < 4; mi++)
            #pragma unroll
            for (int j = 0; j < 8; j++)
                #pragma unroll
                for (int e = 0; e < 4; e++) {
                    float v = acc[mi][j][e];
                    sum += v;
                    ss  += v * v;
                }
        #pragma unroll
        for (int off = 16; off; off >>= 1) {
            sum += __shfl_xor_sync(0xffffffffu, sum, off);
            ss  += __shfl_xor_sync(0xffffffffu, ss, off);
        }
        __syncthreads();
        float* red = (float*)sh;
        if (lane == 0) { red[warp * 2] = sum; red[warp * 2 + 1] = ss; }
        __syncthreads();
        if (tid < 4) {
            float s = red[(tid * 2) * 2]     + red[(tid * 2 + 1) * 2];
            float q = red[(tid * 2) * 2 + 1] + red[(tid * 2 + 1) * 2 + 1];
            int grp = (row0 >> 6) + tid;
            g_gnp[((bz * 8 + grp) * 8 + blockIdx.x) * 2]     = s;
            g_gnp[((bz * 8 + grp) * 8 + blockIdx.x) * 2 + 1] = q;
        }
    }
}

// ---------------------------------------------------------------------------
// Fused flash attention: 128 rows, 4 warps, 1 barrier/tile, ones-mma sums,
// f16x2 exp producing P fragments directly (halves MUFU ops).
// ---------------------------------------------------------------------------
#define LDQ 136
#define LDK 72
#define LDO 72
#define ATT_SMEM ((64 * LDQ + 4 * 64 * LDK) * 2)
#define ONES2 0x3C003C00u

__global__ __launch_bounds__(128) void attn_h(
    const __half* __restrict__ qkv, __half* __restrict__ outh)
{
    extern __shared__ __half smh[];
    __half* qs = smh;
    __half* kv = smh + 64 * LDQ;

    const int b = blockIdx.z, h = blockIdx.y;
    const int n0 = blockIdx.x * 128;
    const int tid = threadIdx.x, warp = tid >> 5, lane = tid & 31;
    const int g = lane >> 2, t = lane & 3;
    const int rowbase = warp * 32;

    const __half* q = qkv + (((size_t)b * 3 + 0) * NH + h) * HD * NN;
    const __half* k = qkv + (((size_t)b * 3 + 1) * NH + h) * HD * NN;
    const __half* v = qkv + (((size_t)b * 3 + 2) * NH + h) * HD * NN;

    const uint32_t qb  = smem_u32(qs);
    const uint32_t kvb = smem_u32(kv);
    const uint32_t qLane = ((((lane & 7) + 8 * (lane >> 4)) * LDQ)
                            + rowbase + 8 * ((lane >> 3) & 1)) * 2;
    const uint32_t kLane = ((((lane & 7) + 8 * ((lane >> 3) & 1)) * LDK)
                            + 8 * (lane >> 4)) * 2;
    const uint32_t vLane = ((((lane & 7) + 8 * (lane >> 4)) * LDK)
                            + 8 * ((lane >> 3) & 1)) * 2;

    auto issueKV = [&](int mt, int st) {
        const int m0 = mt * 64;
        const uint32_t kd = kvb + st * (2 * 64 * LDK) * 2;
        const uint32_t vd = kd + (64 * LDK) * 2;
        #pragma unroll
        for (int i = 0; i < 4; i++) {
            int idx = tid + i * 128;
            int d = idx >> 3, ch = idx & 7;
            cp_async16(kd + (d * LDK + ch * 8) * 2, k + (size_t)d * NN + m0 + ch * 8);
            cp_async16(vd + (d * LDK + ch * 8) * 2, v + (size_t)d * NN + m0 + ch * 8);
        }
    };

    #pragma unroll
    for (int i = 0; i < 8; i++) {
        int idx = tid + i * 128;
        int d = idx >> 4, ch = idx & 15;
        cp_async16(qb + (d * LDQ + ch * 8) * 2, q + (size_t)d * NN + n0 + ch * 8);
    }
    issueKV(0, 0);
    CP_COMMIT();

    float o[2][8][4];
    float Mx[2][2], L[2][2];
    #pragma unroll
    for (int i = 0; i < 2; i++) {
        #pragma unroll
        for (int j = 0; j < 8; j++)
            #pragma unroll
            for (int e = 0; e < 4; e++) o[i][j][e] = 0.f;
        Mx[i][0] = Mx[i][1] = -1e30f;
        L[i][0] = L[i][1] = 0.f;
    }

    for (int mt = 0; mt < NN / 64; mt++) {
        const int st = mt & 1;
        CP_WAIT(0);
        __syncthreads();
        if (mt + 1 < NN / 64) {
            issueKV(mt + 1, st ^ 1);
            CP_COMMIT();
        }

        const uint32_t kAddr = kvb + st * (2 * 64 * LDK) * 2 + kLane;
        const uint32_t vAddr = kvb + st * (2 * 64 * LDK) * 2 + (64 * LDK) * 2 + vLane;

        // ---- S = Q * K^T ----
        float s[2][8][4];
        #pragma unroll
        for (int i = 0; i < 2; i++)
            #pragma unroll
            for (int j = 0; j < 8; j++)
                #pragma unroll
                for (int e = 0; e < 4; e++) s[i][j][e] = 0.f;

        #pragma unroll
        for (int ks16 = 0; ks16 < 4; ks16++) {
            uint32_t a[2][4];
            ldsm4t(a[0], qb + qLane + ks16 * 16 * LDQ * 2);
            ldsm4t(a[1], qb + qLane + ks16 * 16 * LDQ * 2 + 32);
            #pragma unroll
            for (int jj = 0; jj < 4; jj++) {
                uint32_t bf[4];
                ldsm4t(bf, kAddr + ks16 * 16 * LDK * 2 + jj * 32);
                mma16816(s[0][2 * jj],     a[0], bf[0], bf[1]);
                mma16816(s[0][2 * jj + 1], a[0], bf[2], bf[3]);
                mma16816(s[1][2 * jj],     a[1], bf[0], bf[1]);
                mma16816(s[1][2 * jj + 1], a[1], bf[2], bf[3]);
            }
        }

        // ---- online softmax: f16x2 exp -> P fragments directly ----
        uint32_t P[2][2][8];
        #pragma unroll
        for (int i = 0; i < 2; i++) {
            #pragma unroll
            for (int rh = 0; rh < 2; rh++) {
                float tm = -1e30f;
                #pragma unroll
                for (int j = 0; j < 8; j++)
                    tm = fmaxf(tm, fmaxf(s[i][j][2 * rh], s[i][j][2 * rh + 1]));
                tm = fmaxf(tm, __shfl_xor_sync(0xffffffffu, tm, 1));
                tm = fmaxf(tm, __shfl_xor_sync(0xffffffffu, tm, 2));
                float nM = fmaxf(Mx[i][rh], tm);
                float corr = exp2f(Mx[i][rh] - nM);
                Mx[i][rh] = nM;
                #pragma unroll
                for (int j = 0; j < 8; j++)
                    P[i][rh][j] = h2exp2(pk(s[i][j][2 * rh] - nM,
                                            s[i][j][2 * rh + 1] - nM));
                L[i][rh] *= corr;
                #pragma unroll
                for (int j = 0; j < 8; j++) {
                    o[i][j][2 * rh]     *= corr;
                    o[i][j][2 * rh + 1] *= corr;
                }
            }
        }

        // ---- O += P * V^T ; L += P * 1 (ones-mma) ----
        float lsa[2][4];
        #pragma unroll
        for (int i = 0; i < 2; i++)
            #pragma unroll
            for (int e = 0; e < 4; e++) lsa[i][e] = 0.f;

        #pragma unroll
        for (int ms2 = 0; ms2 < 4; ms2++) {
            uint32_t aP[2][4];
            #pragma unroll
            for (int i = 0; i < 2; i++) {
                aP[i][0] = P[i][0][2 * ms2];
                aP[i][1] = P[i][1][2 * ms2];
                aP[i][2] = P[i][0][2 * ms2 + 1];
                aP[i][3] = P[i][1][2 * ms2 + 1];
            }
            #pragma unroll
            for (int jj = 0; jj < 4; jj++) {
                uint32_t bf[4];
                ldsm4(bf, vAddr + jj * 16 * LDK * 2 + ms2 * 32);
                mma16816(o[0][2 * jj],     aP[0], bf[0], bf[1]);
                mma16816(o[0][2 * jj + 1], aP[0], bf[2], bf[3]);
                mma16816(o[1][2 * jj],     aP[1], bf[0], bf[1]);
                mma16816(o[1][2 * jj + 1], aP[1], bf[2], bf[3]);
            }
            mma16816(lsa[0], aP[0], ONES2, ONES2);
            mma16816(lsa[1], aP[1], ONES2, ONES2);
        }
        #pragma unroll
        for (int i = 0; i < 2; i++) {
            L[i][0] += lsa[i][0];
            L[i][1] += lsa[i][2];
        }
    }

    __syncthreads();
    __half* os = smh;
    #pragma unroll
    for (int i = 0; i < 2; i++) {
        float inv0 = 1.f / L[i][0];
        float inv1 = 1.f / L[i][1];
        int rl = rowbase + 16 * i + g;
        #pragma unroll
        for (int j = 0; j < 8; j++) {
            int d = 8 * j + 2 * t;
            *(uint32_t*)&os[rl * LDO + d]       = pk(o[i][j][0] * inv0, o[i][j][1] * inv0);
            *(uint32_t*)&os[(rl + 8) * LDO + d] = pk(o[i][j][2] * inv1, o[i][j][3] * inv1);
        }
    }
    __syncthreads();
    {
        const int d = tid >> 1, seg = (tid & 1) * 64;
        __half* dst = outh + ((size_t)b * CH + h * HD + d) * NN + n0 + seg;
        #pragma unroll
        for (int c8 = 0; c8 < 8; c8++) {
            __half tmp[8];
            #pragma unroll
            for (int r = 0; r < 8; r++)
                tmp[r] = os[(seg + c8 * 8 + r) * LDO + d];
            *(uint4*)&dst[c8 * 8] = *(uint4*)tmp;
        }
    }
}

// ---------------------------------------------------------------------------
// GroupNorm apply (stats from GEMM-epilogue partials) + residual
// ---------------------------------------------------------------------------
__global__ __launch_bounds__(256) void gn_apply(
    const __half* __restrict__ p, const float* __restrict__ x,
    const float* __restrict__ gamma, const float* __restrict__ beta,
    float* __restrict__ out)
{
    const int bg = blockIdx.x >> 3, sp = blockIdx.x & 7;
    float sum = 0.f, ss = 0.f;
    #pragma unroll
    for (int xk = 0; xk < 8; xk++) {
        sum += g_gnp[(bg * 8 + xk) * 2];
        ss  += g_gnp[(bg * 8 + xk) * 2 + 1];
    }
    const float invn = 1.f / 65536.f;
    const float mean = sum * invn;
    const float inv  = rsqrtf(ss * invn - mean * mean + GN_EPS);
    const int grp = bg & 7;

    const size_t base = (size_t)bg * CPG * NN;
    const uint4*  p8 = (const uint4*)(p + base) + sp * 1024;
    const float4* x4 = (const float4*)(x + base) + sp * 2048;
    float4*       o4 = (float4*)(out + base) + sp * 2048;

    #pragma unroll
    for (int it = 0; it < 4; it++) {
        int idx = threadIdx.x + it * 256;
        int c = grp * CPG + sp * 8 + (idx >> 7);
        float ga = gamma[c] * inv, be = beta[c];
        uint4 u = p8[idx];
        const __half2* hp = (const __half2*)&u;
        float4 xa = x4[2 * idx], xb = x4[2 * idx + 1];
        float2 f0 = __half22float2(hp[0]), f1 = __half22float2(hp[1]);
        float2 f2 = __half22float2(hp[2]), f3 = __half22float2(hp[3]);
        float4 ra, rb;
        ra.x = (f0.x - mean) * ga + be + xa.x;
        ra.y = (f0.y - mean) * ga + be + xa.y;
        ra.z = (f1.x - mean) * ga + be + xa.z;
        ra.w = (f1.y - mean) * ga + be + xa.w;
        rb.x = (f2.x - mean) * ga + be + xb.x;
        rb.y = (f2.y - mean) * ga + be + xb.y;
        rb.z = (f3.x - mean) * ga + be + xb.z;
        rb.w = (f3.y - mean) * ga + be + xb.w;
        o4[2 * idx]     = ra;
        o4[2 * idx + 1] = rb;
    }
}

// ---------------------------------------------------------------------------
extern "C" void kernel_launch(void* const* d_in, const int* in_sizes, int n_in,
                              void* d_out, int out_size)
{
    const float* x      = (const float*)d_in[0];
    const float* w_qkv  = (const float*)d_in[1];
    const float* w_proj = (const float*)d_in[2];
    const float* gamma  = (const float*)d_in[3];
    const float* beta   = (const float*)d_in[4];
    float* out = (float*)d_out;

    __half *w16, *wp16, *x16, *qkvh, *atth, *projh;
    cudaGetSymbolAddress((void**)&w16,   g_w16);
    cudaGetSymbolAddress((void**)&wp16,  g_wp16);
    cudaGetSymbolAddress((void**)&x16,   g_x16);
    cudaGetSymbolAddress((void**)&qkvh,  g_qkvh);
    cudaGetSymbolAddress((void**)&atth,  g_atth);
    cudaGetSymbolAddress((void**)&projh, g_projh);

    static bool attr_set = false;
    if (!attr_set) {
        cudaFuncSetAttribute(attn_h,
            cudaFuncAttributeMaxDynamicSharedMemorySize, ATT_SMEM);
        cudaFuncSetAttribute((const void*)gemm_a<__half, true, false>,
            cudaFuncAttributeMaxDynamicSharedMemorySize, GSMEM);
        cudaFuncSetAttribute((const void*)gemm_a<__half, false, true>,
            cudaFuncAttributeMaxDynamicSharedMemorySize, GSMEM);
        attr_set = true;
    }

    // 0) single-launch fp32 -> fp16 conversion
    cvt_all<<<1280, 256>>>(w_qkv, w16, w_proj, wp16, x, x16);

    // 1) QKV projection (Q rows scaled by 0.125*log2e), 256x128 tiles, k64
    gemm_a<__half, true, false><<<dim3(NN / 128, (3 * CH) / 256, BATCH), 256, GSMEM>>>(
        w16, x16, qkvh, 3 * CH, NN, CH);

    // 2) Fused flash attention (f16x2 exp softmax)
    attn_h<<<dim3(NN / 128, NH, BATCH), 128, ATT_SMEM>>>(qkvh, atth);

    // 3) Output projection -> fp16, GN partials fused into epilogue, k64
    gemm_a<__half, false, true><<<dim3(NN / 128, CH / 256, BATCH), 256, GSMEM>>>(
        wp16, atth, projh, CH, NN, CH);

    // 4) GroupNorm apply + residual (stats from fused partials)
    gn_apply<<<512, 256>>>(projh, x, gamma, beta, out);
}